// round 1
// baseline (speedup 1.0000x reference)
#include <cuda_runtime.h>
#include <math.h>

#define B_    2
#define L_    2048
#define D_    1024
#define FFN_  4096
#define NH_   8
#define HD_   128
#define BL_   (B_ * L_)            // 4096 rows
#define CHUNK_ ((long long)L_ * HD_) // 262144 per (b,head)
#define LN_EPS 1e-5f
#define RSQRT_HD 0.08838834764831845f

// ---------------- scratch (device globals: allocation-free) ----------------
__device__ float g_q  [BL_ * D_];
__device__ float g_k  [BL_ * D_];
__device__ float g_v  [BL_ * D_];
__device__ float g_ctx[BL_ * D_];
__device__ float g_hsa[BL_ * D_];
__device__ float g_h1 [BL_ * D_];
__device__ float g_hf [BL_ * D_];
__device__ float g_ffn[(size_t)BL_ * FFN_];
__device__ float g_s  [(size_t)B_ * NH_ * L_ * L_];   // 268 MB score scratch
__device__ float g_rq [BL_ * 4];
__device__ float g_rk [BL_ * 4];

// ---------------- generic batched SGEMM: C = op(alpha*A@B + bias) ----------
// Tiles: 128x128x8, 256 threads, 8x8 per-thread micro-tile, double-buffered.
// Requires M%128==0, N%128==0, K%8==0 (true for every call here).
__global__ __launch_bounds__(256)
void sgemm_kernel(const float* __restrict__ A, const float* __restrict__ Bm,
                  const float* __restrict__ bias, float* __restrict__ C,
                  int K, int lda, int ldb, int ldc,
                  long long sA, long long sB, long long sC,
                  float alpha, int doBias, int doRelu)
{
    __shared__ float As[2][8][128];
    __shared__ float Bs[2][8][128];

    const int bz = blockIdx.z;
    A  += (long long)bz * sA;
    Bm += (long long)bz * sB;
    C  += (long long)bz * sC;

    const int rowTile = blockIdx.y * 128;
    const int colTile = blockIdx.x * 128;
    const int tid = threadIdx.x;
    const int tx = tid & 15;     // 16 col-groups
    const int ty = tid >> 4;     // 16 row-groups

    // global-load assignments (one float4 each for A and B per tile)
    const int aRow = tid >> 1;          // 0..127
    const int aCol = (tid & 1) * 4;     // 0 or 4
    const int bRow = tid >> 5;          // 0..7
    const int bCol = (tid & 31) * 4;    // 0..124

    float acc[8][8];
#pragma unroll
    for (int i = 0; i < 8; i++)
#pragma unroll
        for (int j = 0; j < 8; j++) acc[i][j] = 0.f;

    const int nT = K >> 3;

    // prologue: tile 0 -> buffer 0
    {
        float4 a4 = *(const float4*)(A + (long long)(rowTile + aRow) * lda + aCol);
        As[0][aCol + 0][aRow] = a4.x;
        As[0][aCol + 1][aRow] = a4.y;
        As[0][aCol + 2][aRow] = a4.z;
        As[0][aCol + 3][aRow] = a4.w;
        *(float4*)&Bs[0][bRow][bCol] =
            *(const float4*)(Bm + (long long)bRow * ldb + colTile + bCol);
    }

    int cur = 0;
    for (int t = 0; t < nT; ++t) {
        __syncthreads();
        float4 a4, b4;
        const bool more = (t + 1 < nT);
        if (more) {
            const int k0 = (t + 1) << 3;
            a4 = *(const float4*)(A + (long long)(rowTile + aRow) * lda + k0 + aCol);
            b4 = *(const float4*)(Bm + (long long)(k0 + bRow) * ldb + colTile + bCol);
        }
#pragma unroll
        for (int k = 0; k < 8; ++k) {
            float4 a0 = *(const float4*)&As[cur][k][ty * 4];
            float4 a1 = *(const float4*)&As[cur][k][64 + ty * 4];
            float4 b0 = *(const float4*)&Bs[cur][k][tx * 4];
            float4 b1 = *(const float4*)&Bs[cur][k][64 + tx * 4];
            float ar[8] = {a0.x, a0.y, a0.z, a0.w, a1.x, a1.y, a1.z, a1.w};
            float br[8] = {b0.x, b0.y, b0.z, b0.w, b1.x, b1.y, b1.z, b1.w};
#pragma unroll
            for (int i = 0; i < 8; i++)
#pragma unroll
                for (int j = 0; j < 8; j++)
                    acc[i][j] = fmaf(ar[i], br[j], acc[i][j]);
        }
        if (more) {
            const int nxt = cur ^ 1;
            As[nxt][aCol + 0][aRow] = a4.x;
            As[nxt][aCol + 1][aRow] = a4.y;
            As[nxt][aCol + 2][aRow] = a4.z;
            As[nxt][aCol + 3][aRow] = a4.w;
            *(float4*)&Bs[nxt][bRow][bCol] = b4;
            cur = nxt;
        }
    }

    // epilogue
#pragma unroll
    for (int i = 0; i < 8; i++) {
        const int r = rowTile + ((i < 4) ? (ty * 4 + i) : (64 + ty * 4 + (i - 4)));
#pragma unroll
        for (int jh = 0; jh < 2; jh++) {
            const int c = colTile + jh * 64 + tx * 4;
            float4 o;
            o.x = alpha * acc[i][jh * 4 + 0];
            o.y = alpha * acc[i][jh * 4 + 1];
            o.z = alpha * acc[i][jh * 4 + 2];
            o.w = alpha * acc[i][jh * 4 + 3];
            if (doBias) {
                o.x += bias[c + 0]; o.y += bias[c + 1];
                o.z += bias[c + 2]; o.w += bias[c + 3];
            }
            if (doRelu) {
                o.x = fmaxf(o.x, 0.f); o.y = fmaxf(o.y, 0.f);
                o.z = fmaxf(o.z, 0.f); o.w = fmaxf(o.w, 0.f);
            }
            *(float4*)&C[(long long)r * ldc + c] = o;
        }
    }
}

// ---------------- rank-4 relative projections ----------------
__global__ void rproj_kernel(const float* __restrict__ rh,
                             const float* __restrict__ Wrq,
                             const float* __restrict__ Wrk,
                             float* __restrict__ rq, float* __restrict__ rk)
{
    const int i = blockIdx.x * blockDim.x + threadIdx.x;   // 0 .. BL_-1
    if (i >= BL_) return;
    const float h0 = rh[i * 4 + 0], h1v = rh[i * 4 + 1];
    const float h2 = rh[i * 4 + 2], h3 = rh[i * 4 + 3];
#pragma unroll
    for (int r = 0; r < 4; r++) {
        rq[i * 4 + r] = h0 * Wrq[r] + h1v * Wrq[4 + r] + h2 * Wrq[8 + r] + h3 * Wrq[12 + r];
        rk[i * 4 + r] = h0 * Wrk[r] + h1v * Wrk[4 + r] + h2 * Wrk[8 + r] + h3 * Wrk[12 + r];
    }
}

// ---------------- block reductions ----------------
__device__ __forceinline__ float blockReduce(float v, float* red, bool isMax)
{
    __syncthreads();   // protect `red` across consecutive calls
#pragma unroll
    for (int o = 16; o > 0; o >>= 1) {
        float t = __shfl_xor_sync(0xffffffffu, v, o);
        v = isMax ? fmaxf(v, t) : (v + t);
    }
    const int warp = threadIdx.x >> 5, lane = threadIdx.x & 31;
    if (lane == 0) red[warp] = v;
    __syncthreads();
    if (warp == 0) {
        v = (lane < 8) ? red[lane] : (isMax ? -INFINITY : 0.f);
#pragma unroll
        for (int o = 4; o > 0; o >>= 1) {
            float t = __shfl_xor_sync(0xffffffffu, v, o);
            v = isMax ? fmaxf(v, t) : (v + t);
        }
        if (lane == 0) red[0] = v;
    }
    __syncthreads();
    return red[0];
}

// ---------------- fused rel-bias + softmax (in place on g_s) ----------------
// grid: (L_, NH_, B_), 256 threads; each thread owns 8 columns.
__global__ __launch_bounds__(256)
void softmax_bias_kernel(float* __restrict__ S,
                         const float* __restrict__ rq,
                         const float* __restrict__ rk)
{
    __shared__ float red[32];
    const int l = blockIdx.x, n = blockIdx.y, b = blockIdx.z;
    float* row = S + ((((long long)b * NH_ + n) * L_) + l) * L_;
    const float* rqp = rq + ((long long)b * L_ + l) * 4;
    const float* rkp = rk + (long long)b * L_ * 4;   // flat reinterpret: idx r*L + m
    const float q0 = rqp[0] * 0.5f, q1 = rqp[1] * 0.5f;
    const float q2 = rqp[2] * 0.5f, q3 = rqp[3] * 0.5f;
    const int tid = threadIdx.x;

    float vals[8];
    float vmax = -INFINITY;
#pragma unroll
    for (int j = 0; j < 8; j++) {
        const int m = j * 256 + tid;
        const float bias = q0 * rkp[m] + q1 * rkp[L_ + m]
                         + q2 * rkp[2 * L_ + m] + q3 * rkp[3 * L_ + m];
        const float v = row[m] + bias;
        vals[j] = v;
        vmax = fmaxf(vmax, v);
    }
    vmax = blockReduce(vmax, red, true);

    float sum = 0.f;
#pragma unroll
    for (int j = 0; j < 8; j++) {
        vals[j] = __expf(vals[j] - vmax);
        sum += vals[j];
    }
    sum = blockReduce(sum, red, false);
    const float inv = 1.f / sum;
#pragma unroll
    for (int j = 0; j < 8; j++)
        row[j * 256 + tid] = vals[j] * inv;
}

// ---------------- fused residual-add + LayerNorm ----------------
// grid: BL_ blocks, 256 threads, D_=1024 -> 4 elements/thread.
__global__ __launch_bounds__(256)
void add_ln_kernel(const float* __restrict__ x, const float* __restrict__ y,
                   const float* __restrict__ g, const float* __restrict__ be,
                   float* __restrict__ out)
{
    __shared__ float red[32];
    const long long row = blockIdx.x;
    const float* xp = x + row * D_;
    const float* yp = y + row * D_;
    float* op = out + row * D_;
    const int tid = threadIdx.x;

    float v[4];
    float s = 0.f;
#pragma unroll
    for (int j = 0; j < 4; j++) {
        const int i = j * 256 + tid;
        v[j] = xp[i] + yp[i];
        s += v[j];
    }
    const float mean = blockReduce(s, red, false) * (1.f / D_);

    float sq = 0.f;
#pragma unroll
    for (int j = 0; j < 4; j++) {
        const float d = v[j] - mean;
        sq += d * d;
    }
    const float var = blockReduce(sq, red, false) * (1.f / D_);
    const float rstd = rsqrtf(var + LN_EPS);
#pragma unroll
    for (int j = 0; j < 4; j++) {
        const int i = j * 256 + tid;
        op[i] = (v[j] - mean) * rstd * g[i] + be[i];
    }
}

// ---------------- host-side launcher helpers ----------------
static void sgemm(const float* A, const float* Bm, const float* bias, float* C,
                  int M, int N, int K, int lda, int ldb, int ldc,
                  long long sA, long long sB, long long sC, int batch,
                  float alpha, int doBias, int doRelu)
{
    dim3 grid(N / 128, M / 128, batch), block(256);
    sgemm_kernel<<<grid, block>>>(A, Bm, bias, C, K, lda, ldb, ldc,
                                  sA, sB, sC, alpha, doBias, doRelu);
}

extern "C" void kernel_launch(void* const* d_in, const int* in_sizes, int n_in,
                              void* d_out, int out_size)
{
    const float* h   = (const float*)d_in[0];
    const float* rh  = (const float*)d_in[1];
    const float* Wq  = (const float*)d_in[2];
    const float* Wk  = (const float*)d_in[3];
    const float* Wv  = (const float*)d_in[4];
    const float* Wo  = (const float*)d_in[5];
    const float* Wrk = (const float*)d_in[6];
    const float* Wrq = (const float*)d_in[7];
    const float* W1  = (const float*)d_in[8];
    const float* b1  = (const float*)d_in[9];
    const float* W2  = (const float*)d_in[10];
    const float* b2  = (const float*)d_in[11];
    const float* g1  = (const float*)d_in[12];
    const float* be1 = (const float*)d_in[13];
    const float* g2  = (const float*)d_in[14];
    const float* be2 = (const float*)d_in[15];
    float* out = (float*)d_out;

    float *q, *k, *v, *ctx, *hsa, *h1, *hf, *ffn, *s, *rq, *rk;
    cudaGetSymbolAddress((void**)&q,   g_q);
    cudaGetSymbolAddress((void**)&k,   g_k);
    cudaGetSymbolAddress((void**)&v,   g_v);
    cudaGetSymbolAddress((void**)&ctx, g_ctx);
    cudaGetSymbolAddress((void**)&hsa, g_hsa);
    cudaGetSymbolAddress((void**)&h1,  g_h1);
    cudaGetSymbolAddress((void**)&hf,  g_hf);
    cudaGetSymbolAddress((void**)&ffn, g_ffn);
    cudaGetSymbolAddress((void**)&s,   g_s);
    cudaGetSymbolAddress((void**)&rq,  g_rq);
    cudaGetSymbolAddress((void**)&rk,  g_rk);

    // 1) Q/K/V projections: [4096,1024] @ [1024,1024]
    sgemm(h, Wq, nullptr, q, BL_, D_, D_, D_, D_, D_, 0, 0, 0, 1, 1.f, 0, 0);
    sgemm(h, Wk, nullptr, k, BL_, D_, D_, D_, D_, D_, 0, 0, 0, 1, 1.f, 0, 0);
    sgemm(h, Wv, nullptr, v, BL_, D_, D_, D_, D_, D_, 0, 0, 0, 1, 1.f, 0, 0);

    // 2) rank-4 relative projections
    rproj_kernel<<<BL_ / 256, 256>>>(rh, Wrq, Wrk, rq, rk);

    // 3) scores: per (b,head) chunk, S = (Q_chunk[2048x128] @ K_chunk-as-[128x2048]) / sqrt(128)
    sgemm(q, k, nullptr, s, L_, L_, HD_, HD_, L_, L_,
          CHUNK_, CHUNK_, (long long)L_ * L_, B_ * NH_, RSQRT_HD, 0, 0);

    // 4) fused rel-bias + softmax, in place
    {
        dim3 grid(L_, NH_, B_);
        softmax_bias_kernel<<<grid, 256>>>(s, rq, rk);
    }

    // 5) context: P[2048x2048] @ V_chunk[2048x128]; flat ctx buffer == context.reshape(B,L,D)
    sgemm(s, v, nullptr, ctx, L_, HD_, L_, L_, HD_, HD_,
          (long long)L_ * L_, CHUNK_, CHUNK_, B_ * NH_, 1.f, 0, 0);

    // 6) output projection
    sgemm(ctx, Wo, nullptr, hsa, BL_, D_, D_, D_, D_, D_, 0, 0, 0, 1, 1.f, 0, 0);

    // 7) h1 = LN(h_sa + h)
    add_ln_kernel<<<BL_, 256>>>(hsa, h, g1, be1, h1);

    // 8) FFN up: relu(h1 @ W1 + b1)
    sgemm(h1, W1, b1, ffn, BL_, FFN_, D_, D_, FFN_, FFN_, 0, 0, 0, 1, 1.f, 1, 1);

    // 9) FFN down: ffn @ W2 + b2
    sgemm(ffn, W2, b2, hf, BL_, D_, FFN_, FFN_, D_, D_, 0, 0, 0, 1, 1.f, 1, 0);

    // 10) h2 = LN(h1 + hf) -> output
    add_ln_kernel<<<BL_, 256>>>(h1, hf, g2, be2, out);
}

// round 4
// speedup vs baseline: 2.0484x; 2.0484x over previous
#include <cuda_runtime.h>
#include <cuda_bf16.h>
#include <math.h>

#define B_    2
#define L_    2048
#define D_    1024
#define FFN_  4096
#define NH_   8
#define HD_   128
#define BL_   (B_ * L_)
#define CHUNK_ ((long long)L_ * HD_)
#define LN_EPS 1e-5f
#define RSQRT_HD 0.08838834764831845f

// GEMM tiling
#define BM 128
#define BN 128
#define BK 32
#define APITCH 40          // bf16 elems per A smem row
#define BPITCH 136         // bf16 elems per B smem row
#define A_PLANE (BM * APITCH)
#define B_PLANE (BK * BPITCH)
#define SMEM_ELEMS (4 * A_PLANE + 4 * B_PLANE)   // 2 bufs x 2 splits
#define SMEM_BYTES (SMEM_ELEMS * 2)

// ---------------- scratch (device globals: allocation-free) ----------------
__device__ __align__(16) __nv_bfloat16 g_hh [BL_ * D_],  g_hl [BL_ * D_];
__device__ __align__(16) __nv_bfloat16 g_Wqh[D_ * D_],   g_Wql[D_ * D_];
__device__ __align__(16) __nv_bfloat16 g_Wkh[D_ * D_],   g_Wkl[D_ * D_];
__device__ __align__(16) __nv_bfloat16 g_Wvh[D_ * D_],   g_Wvl[D_ * D_];
__device__ __align__(16) __nv_bfloat16 g_Woh[D_ * D_],   g_Wol[D_ * D_];
__device__ __align__(16) __nv_bfloat16 g_W1h[D_ * FFN_], g_W1l[D_ * FFN_];
__device__ __align__(16) __nv_bfloat16 g_W2h[FFN_ * D_], g_W2l[FFN_ * D_];
__device__ __align__(16) __nv_bfloat16 g_qh [BL_ * D_],  g_ql [BL_ * D_];
__device__ __align__(16) __nv_bfloat16 g_kh [BL_ * D_],  g_kl [BL_ * D_];
__device__ __align__(16) __nv_bfloat16 g_vh [BL_ * D_],  g_vl [BL_ * D_];
__device__ __align__(16) __nv_bfloat16 g_ch [BL_ * D_],  g_cl [BL_ * D_];
__device__ __align__(16) __nv_bfloat16 g_h1h[BL_ * D_],  g_h1l[BL_ * D_];
__device__ __align__(16) __nv_bfloat16 g_fh [(size_t)BL_ * FFN_], g_fl[(size_t)BL_ * FFN_];
__device__ __align__(16) __nv_bfloat16 g_Ph [(size_t)B_ * NH_ * L_ * L_];
__device__ __align__(16) __nv_bfloat16 g_Pl [(size_t)B_ * NH_ * L_ * L_];
__device__ float g_S  [(size_t)B_ * NH_ * L_ * L_];
__device__ float g_hsa[BL_ * D_];
__device__ float g_h1 [BL_ * D_];
__device__ float g_hf [BL_ * D_];
__device__ float g_rq [BL_ * 4];
__device__ float g_rk [BL_ * 4];

// ---------------- helpers ----------------
__device__ __forceinline__ void splitf(float x, __nv_bfloat16& h, __nv_bfloat16& l)
{
    h = __float2bfloat16(x);
    l = __float2bfloat16(x - __bfloat162float(h));
}

#define LDSM4(R, addr) asm volatile( \
    "ldmatrix.sync.aligned.m8n8.x4.shared.b16 {%0,%1,%2,%3}, [%4];" \
    : "=r"((R)[0]), "=r"((R)[1]), "=r"((R)[2]), "=r"((R)[3]) : "r"(addr))

#define LDSM4T(R, addr) asm volatile( \
    "ldmatrix.sync.aligned.m8n8.x4.trans.shared.b16 {%0,%1,%2,%3}, [%4];" \
    : "=r"((R)[0]), "=r"((R)[1]), "=r"((R)[2]), "=r"((R)[3]) : "r"(addr))

#define MMA16816(AC, A, B0, B1) asm volatile( \
    "mma.sync.aligned.m16n8k16.row.col.f32.bf16.bf16.f32 " \
    "{%0,%1,%2,%3},{%4,%5,%6,%7},{%8,%9},{%0,%1,%2,%3};" \
    : "+f"((AC)[0]), "+f"((AC)[1]), "+f"((AC)[2]), "+f"((AC)[3]) \
    : "r"((A)[0]), "r"((A)[1]), "r"((A)[2]), "r"((A)[3]), "r"(B0), "r"(B1))

// ---------------- split-bf16 tensor-core GEMM ----------------
// C = op(alpha * (Ah+Al)@(Bh+Bl) + bias), dropping Al@Bl.
// A row-major [M,K] (lda), B row-major [K,N] (ldb). M%128==0, N%128==0, K%32==0.
__global__ __launch_bounds__(256, 1)
void gemm_bf16s_kernel(const __nv_bfloat16* __restrict__ Ah, const __nv_bfloat16* __restrict__ Al,
                       const __nv_bfloat16* __restrict__ Bh, const __nv_bfloat16* __restrict__ Bl,
                       const float* __restrict__ bias,
                       float* __restrict__ Cf, __nv_bfloat16* __restrict__ Ch,
                       __nv_bfloat16* __restrict__ Cl,
                       int K, int lda, int ldb, int ldc,
                       long long sA, long long sB, long long sC,
                       float alpha, int doBias, int doRelu)
{
    extern __shared__ __nv_bfloat16 smem[];
    __nv_bfloat16* As = smem;                    // 4 planes: (buf*2 + split)
    __nv_bfloat16* Bs = smem + 4 * A_PLANE;

    const int bz = blockIdx.z;
    Ah += (long long)bz * sA;  Al += (long long)bz * sA;
    Bh += (long long)bz * sB;  Bl += (long long)bz * sB;
    const long long cOff = (long long)bz * sC;

    const int rowTile = blockIdx.y * BM, colTile = blockIdx.x * BN;
    const int tid = threadIdx.x, lane = tid & 31, w = tid >> 5;
    const int wRow = (w >> 2) * 64, wCol = (w & 3) * 32;

    // ---- global loader mapping: full tile coverage ----
    // A plane: 128x32 = 512 uint4. thread handles uint4 {tid, tid+256}.
    //   u -> row u>>2, col (u&3)*8   (4 uint4 per 32-wide row)
    // B plane: 32x128 = 512 uint4. thread handles uint4 {tid, tid+256}.
    //   u -> row u>>4, col (u&15)*8  (16 uint4 per 128-wide row)
    const int aR0 = tid >> 2,  aC0 = (tid & 3) * 8;    // second: row +64
    const int bR0 = tid >> 4,  bC0 = (tid & 15) * 8;   // second: row +16

    const __nv_bfloat16* gAh0 = Ah + (long long)(rowTile + aR0) * lda + aC0;
    const __nv_bfloat16* gAh1 = Ah + (long long)(rowTile + aR0 + 64) * lda + aC0;
    const __nv_bfloat16* gAl0 = Al + (long long)(rowTile + aR0) * lda + aC0;
    const __nv_bfloat16* gAl1 = Al + (long long)(rowTile + aR0 + 64) * lda + aC0;
    const __nv_bfloat16* gBh0 = Bh + (long long)bR0 * ldb + colTile + bC0;
    const __nv_bfloat16* gBh1 = Bh + (long long)(bR0 + 16) * ldb + colTile + bC0;
    const __nv_bfloat16* gBl0 = Bl + (long long)bR0 * ldb + colTile + bC0;
    const __nv_bfloat16* gBl1 = Bl + (long long)(bR0 + 16) * ldb + colTile + bC0;

    const int sA0 = aR0 * APITCH + aC0;
    const int sA1 = (aR0 + 64) * APITCH + aC0;
    const int sB0 = bR0 * BPITCH + bC0;
    const int sB1 = (bR0 + 16) * BPITCH + bC0;

    const unsigned asBase = (unsigned)__cvta_generic_to_shared(As);
    const unsigned bsBase = (unsigned)__cvta_generic_to_shared(Bs);

    // ldmatrix lane offsets
    const int aLR = lane & 15, aLC = (lane >> 4) * 8;
    const int bLR = ((lane >> 3) & 1) * 8 + (lane & 7);
    const int bLC = (lane >> 4) * 8;

    float acc[4][4][4];
#pragma unroll
    for (int i = 0; i < 4; i++)
#pragma unroll
        for (int j = 0; j < 4; j++)
#pragma unroll
            for (int e = 0; e < 4; e++) acc[i][j][e] = 0.f;

    // prologue: tile 0 -> buf 0
    {
        *(uint4*)&As[0 * A_PLANE + sA0] = *(const uint4*)gAh0;
        *(uint4*)&As[0 * A_PLANE + sA1] = *(const uint4*)gAh1;
        *(uint4*)&As[1 * A_PLANE + sA0] = *(const uint4*)gAl0;
        *(uint4*)&As[1 * A_PLANE + sA1] = *(const uint4*)gAl1;
        *(uint4*)&Bs[0 * B_PLANE + sB0] = *(const uint4*)gBh0;
        *(uint4*)&Bs[0 * B_PLANE + sB1] = *(const uint4*)gBh1;
        *(uint4*)&Bs[1 * B_PLANE + sB0] = *(const uint4*)gBl0;
        *(uint4*)&Bs[1 * B_PLANE + sB1] = *(const uint4*)gBl1;
    }
    __syncthreads();

    const int nT = K / BK;
    for (int t = 0; t < nT; ++t) {
        const int cur = t & 1, nxt = cur ^ 1;
        const bool more = (t + 1 < nT);
        uint4 vAh0, vAh1, vAl0, vAl1, vBh0, vBh1, vBl0, vBl1;
        if (more) {
            const long long ka = (long long)(t + 1) * BK;
            vAh0 = *(const uint4*)(gAh0 + ka);
            vAh1 = *(const uint4*)(gAh1 + ka);
            vAl0 = *(const uint4*)(gAl0 + ka);
            vAl1 = *(const uint4*)(gAl1 + ka);
            vBh0 = *(const uint4*)(gBh0 + ka * ldb);
            vBh1 = *(const uint4*)(gBh1 + ka * ldb);
            vBl0 = *(const uint4*)(gBl0 + ka * ldb);
            vBl1 = *(const uint4*)(gBl1 + ka * ldb);
        }

#pragma unroll
        for (int kk = 0; kk < 2; kk++) {
            unsigned ah[4][4], al[4][4], bh[2][4], bl[2][4];
#pragma unroll
            for (int mi = 0; mi < 4; mi++) {
                unsigned adr = asBase + (unsigned)((((cur << 1) + 0) * A_PLANE +
                                (wRow + mi * 16 + aLR) * APITCH + kk * 16 + aLC) << 1);
                LDSM4(ah[mi], adr);
            }
#pragma unroll
            for (int np = 0; np < 2; np++) {
                unsigned adr = bsBase + (unsigned)((((cur << 1) + 0) * B_PLANE +
                                (kk * 16 + bLR) * BPITCH + wCol + np * 16 + bLC) << 1);
                LDSM4T(bh[np], adr);
            }
#pragma unroll
            for (int mi = 0; mi < 4; mi++)
#pragma unroll
                for (int ni = 0; ni < 4; ni++)
                    MMA16816(acc[mi][ni], ah[mi], bh[ni >> 1][(ni & 1) * 2], bh[ni >> 1][(ni & 1) * 2 + 1]);

#pragma unroll
            for (int mi = 0; mi < 4; mi++) {
                unsigned adr = asBase + (unsigned)((((cur << 1) + 1) * A_PLANE +
                                (wRow + mi * 16 + aLR) * APITCH + kk * 16 + aLC) << 1);
                LDSM4(al[mi], adr);
            }
#pragma unroll
            for (int mi = 0; mi < 4; mi++)
#pragma unroll
                for (int ni = 0; ni < 4; ni++)
                    MMA16816(acc[mi][ni], al[mi], bh[ni >> 1][(ni & 1) * 2], bh[ni >> 1][(ni & 1) * 2 + 1]);

#pragma unroll
            for (int np = 0; np < 2; np++) {
                unsigned adr = bsBase + (unsigned)((((cur << 1) + 1) * B_PLANE +
                                (kk * 16 + bLR) * BPITCH + wCol + np * 16 + bLC) << 1);
                LDSM4T(bl[np], adr);
            }
#pragma unroll
            for (int mi = 0; mi < 4; mi++)
#pragma unroll
                for (int ni = 0; ni < 4; ni++)
                    MMA16816(acc[mi][ni], ah[mi], bl[ni >> 1][(ni & 1) * 2], bl[ni >> 1][(ni & 1) * 2 + 1]);
        }

        if (more) {
            *(uint4*)&As[(nxt * 2 + 0) * A_PLANE + sA0] = vAh0;
            *(uint4*)&As[(nxt * 2 + 0) * A_PLANE + sA1] = vAh1;
            *(uint4*)&As[(nxt * 2 + 1) * A_PLANE + sA0] = vAl0;
            *(uint4*)&As[(nxt * 2 + 1) * A_PLANE + sA1] = vAl1;
            *(uint4*)&Bs[(nxt * 2 + 0) * B_PLANE + sB0] = vBh0;
            *(uint4*)&Bs[(nxt * 2 + 0) * B_PLANE + sB1] = vBh1;
            *(uint4*)&Bs[(nxt * 2 + 1) * B_PLANE + sB0] = vBl0;
            *(uint4*)&Bs[(nxt * 2 + 1) * B_PLANE + sB1] = vBl1;
            __syncthreads();
        }
    }

    // epilogue
#pragma unroll
    for (int mi = 0; mi < 4; mi++)
#pragma unroll
        for (int ni = 0; ni < 4; ni++) {
            const int r0 = rowTile + wRow + mi * 16 + (lane >> 2);
            const int c  = colTile + wCol + ni * 8 + (lane & 3) * 2;
            float* a = acc[mi][ni];
#pragma unroll
            for (int hrow = 0; hrow < 2; hrow++) {
                const int r = r0 + hrow * 8;
                float o0 = alpha * a[hrow * 2 + 0];
                float o1 = alpha * a[hrow * 2 + 1];
                if (doBias) { o0 += bias[c]; o1 += bias[c + 1]; }
                if (doRelu) { o0 = fmaxf(o0, 0.f); o1 = fmaxf(o1, 0.f); }
                const long long idx = cOff + (long long)r * ldc + c;
                if (Cf) *(float2*)&Cf[idx] = make_float2(o0, o1);
                if (Ch) {
                    __nv_bfloat16 h0, l0, h1, l1;
                    splitf(o0, h0, l0); splitf(o1, h1, l1);
                    __nv_bfloat162 ph; ph.x = h0; ph.y = h1;
                    __nv_bfloat162 pl; pl.x = l0; pl.y = l1;
                    *(__nv_bfloat162*)&Ch[idx] = ph;
                    *(__nv_bfloat162*)&Cl[idx] = pl;
                }
            }
        }
}

// ---------------- fp32 -> bf16 hi/lo split ----------------
__global__ __launch_bounds__(256)
void split_kernel(const float* __restrict__ src, __nv_bfloat16* __restrict__ hi,
                  __nv_bfloat16* __restrict__ lo, long long n)
{
    const long long i = ((long long)blockIdx.x * 256 + threadIdx.x) * 4;
    if (i >= n) return;
    float4 v = *(const float4*)(src + i);
    __nv_bfloat16 h0, l0, h1, l1, h2, l2, h3, l3;
    splitf(v.x, h0, l0); splitf(v.y, h1, l1);
    splitf(v.z, h2, l2); splitf(v.w, h3, l3);
    __nv_bfloat162 a, b;
    a.x = h0; a.y = h1; b.x = h2; b.y = h3;
    *(__nv_bfloat162*)&hi[i] = a; *(__nv_bfloat162*)&hi[i + 2] = b;
    a.x = l0; a.y = l1; b.x = l2; b.y = l3;
    *(__nv_bfloat162*)&lo[i] = a; *(__nv_bfloat162*)&lo[i + 2] = b;
}

// ---------------- rank-4 relative projections ----------------
__global__ void rproj_kernel(const float* __restrict__ rh,
                             const float* __restrict__ Wrq,
                             const float* __restrict__ Wrk,
                             float* __restrict__ rq, float* __restrict__ rk)
{
    const int i = blockIdx.x * blockDim.x + threadIdx.x;
    if (i >= BL_) return;
    const float h0 = rh[i * 4 + 0], h1v = rh[i * 4 + 1];
    const float h2 = rh[i * 4 + 2], h3 = rh[i * 4 + 3];
#pragma unroll
    for (int r = 0; r < 4; r++) {
        rq[i * 4 + r] = h0 * Wrq[r] + h1v * Wrq[4 + r] + h2 * Wrq[8 + r] + h3 * Wrq[12 + r];
        rk[i * 4 + r] = h0 * Wrk[r] + h1v * Wrk[4 + r] + h2 * Wrk[8 + r] + h3 * Wrk[12 + r];
    }
}

// ---------------- block reduction ----------------
__device__ __forceinline__ float blockReduce(float v, float* red, bool isMax)
{
    __syncthreads();
#pragma unroll
    for (int o = 16; o > 0; o >>= 1) {
        float t = __shfl_xor_sync(0xffffffffu, v, o);
        v = isMax ? fmaxf(v, t) : (v + t);
    }
    const int warp = threadIdx.x >> 5, lane = threadIdx.x & 31;
    if (lane == 0) red[warp] = v;
    __syncthreads();
    if (warp == 0) {
        v = (lane < 8) ? red[lane] : (isMax ? -INFINITY : 0.f);
#pragma unroll
        for (int o = 4; o > 0; o >>= 1) {
            float t = __shfl_xor_sync(0xffffffffu, v, o);
            v = isMax ? fmaxf(v, t) : (v + t);
        }
        if (lane == 0) red[0] = v;
    }
    __syncthreads();
    return red[0];
}

// ---------------- fused rel-bias + softmax -> bf16 hi/lo ----------------
__global__ __launch_bounds__(256)
void softmax_bias_kernel(const float* __restrict__ S,
                         const float* __restrict__ rq,
                         const float* __restrict__ rk,
                         __nv_bfloat16* __restrict__ Ph,
                         __nv_bfloat16* __restrict__ Pl)
{
    __shared__ float red[32];
    const int l = blockIdx.x, n = blockIdx.y, b = blockIdx.z;
    const long long rowOff = ((((long long)b * NH_ + n) * L_) + l) * L_;
    const float* row = S + rowOff;
    const float* rqp = rq + ((long long)b * L_ + l) * 4;
    const float* rkp = rk + (long long)b * L_ * 4;
    const float q0 = rqp[0] * 0.5f, q1 = rqp[1] * 0.5f;
    const float q2 = rqp[2] * 0.5f, q3 = rqp[3] * 0.5f;
    const int tid = threadIdx.x;

    float vals[8];
    float vmax = -INFINITY;
#pragma unroll
    for (int j = 0; j < 8; j++) {
        const int m = j * 256 + tid;
        const float bias = q0 * rkp[m] + q1 * rkp[L_ + m]
                         + q2 * rkp[2 * L_ + m] + q3 * rkp[3 * L_ + m];
        const float v = row[m] + bias;
        vals[j] = v;
        vmax = fmaxf(vmax, v);
    }
    vmax = blockReduce(vmax, red, true);

    float sum = 0.f;
#pragma unroll
    for (int j = 0; j < 8; j++) {
        vals[j] = __expf(vals[j] - vmax);
        sum += vals[j];
    }
    sum = blockReduce(sum, red, false);
    const float inv = 1.f / sum;
#pragma unroll
    for (int j = 0; j < 8; j++) {
        const float p = vals[j] * inv;
        __nv_bfloat16 h, lo;
        splitf(p, h, lo);
        Ph[rowOff + j * 256 + tid] = h;
        Pl[rowOff + j * 256 + tid] = lo;
    }
}

// ---------------- fused residual-add + LayerNorm (+ optional split) --------
__global__ __launch_bounds__(256)
void add_ln_kernel(const float* __restrict__ x, const float* __restrict__ y,
                   const float* __restrict__ g, const float* __restrict__ be,
                   float* __restrict__ outF,
                   __nv_bfloat16* __restrict__ outH, __nv_bfloat16* __restrict__ outL)
{
    __shared__ float red[32];
    const long long row = blockIdx.x;
    const float* xp = x + row * D_;
    const float* yp = y + row * D_;
    const int tid = threadIdx.x;

    float v[4];
    float s = 0.f;
#pragma unroll
    for (int j = 0; j < 4; j++) {
        const int i = j * 256 + tid;
        v[j] = xp[i] + yp[i];
        s += v[j];
    }
    const float mean = blockReduce(s, red, false) * (1.f / D_);

    float sq = 0.f;
#pragma unroll
    for (int j = 0; j < 4; j++) {
        const float d = v[j] - mean;
        sq += d * d;
    }
    const float var = blockReduce(sq, red, false) * (1.f / D_);
    const float rstd = rsqrtf(var + LN_EPS);
#pragma unroll
    for (int j = 0; j < 4; j++) {
        const int i = j * 256 + tid;
        const float o = (v[j] - mean) * rstd * g[i] + be[i];
        outF[row * D_ + i] = o;
        if (outH) {
            __nv_bfloat16 h, lo;
            splitf(o, h, lo);
            outH[row * D_ + i] = h;
            outL[row * D_ + i] = lo;
        }
    }
}

// ---------------- host-side helpers ----------------
static void gemm(const __nv_bfloat16* Ah, const __nv_bfloat16* Al,
                 const __nv_bfloat16* Bh, const __nv_bfloat16* Bl,
                 const float* bias, float* Cf, __nv_bfloat16* Ch, __nv_bfloat16* Cl,
                 int M, int N, int K, int lda, int ldb, int ldc,
                 long long sA, long long sB, long long sC, int batch,
                 float alpha, int doBias, int doRelu)
{
    dim3 grid(N / BN, M / BM, batch), block(256);
    gemm_bf16s_kernel<<<grid, block, SMEM_BYTES>>>(Ah, Al, Bh, Bl, bias, Cf, Ch, Cl,
                                                   K, lda, ldb, ldc, sA, sB, sC,
                                                   alpha, doBias, doRelu);
}

static void split(const float* src, __nv_bfloat16* hi, __nv_bfloat16* lo, long long n)
{
    split_kernel<<<(int)(n / 1024), 256>>>(src, hi, lo, n);
}

template <typename T>
static T* sym(T* symbol) { void* p; cudaGetSymbolAddress(&p, (const void*)symbol); return (T*)p; }

extern "C" void kernel_launch(void* const* d_in, const int* in_sizes, int n_in,
                              void* d_out, int out_size)
{
    const float* h   = (const float*)d_in[0];
    const float* rh  = (const float*)d_in[1];
    const float* Wq  = (const float*)d_in[2];
    const float* Wk  = (const float*)d_in[3];
    const float* Wv  = (const float*)d_in[4];
    const float* Wo  = (const float*)d_in[5];
    const float* Wrk = (const float*)d_in[6];
    const float* Wrq = (const float*)d_in[7];
    const float* W1  = (const float*)d_in[8];
    const float* b1  = (const float*)d_in[9];
    const float* W2  = (const float*)d_in[10];
    const float* b2  = (const float*)d_in[11];
    const float* g1  = (const float*)d_in[12];
    const float* be1 = (const float*)d_in[13];
    const float* g2  = (const float*)d_in[14];
    const float* be2 = (const float*)d_in[15];
    float* out = (float*)d_out;

    cudaFuncSetAttribute(gemm_bf16s_kernel,
                         cudaFuncAttributeMaxDynamicSharedMemorySize, SMEM_BYTES);

    __nv_bfloat16 *hh = sym(g_hh), *hl = sym(g_hl);
    __nv_bfloat16 *Wqh = sym(g_Wqh), *Wql = sym(g_Wql);
    __nv_bfloat16 *Wkh = sym(g_Wkh), *Wkl = sym(g_Wkl);
    __nv_bfloat16 *Wvh = sym(g_Wvh), *Wvl = sym(g_Wvl);
    __nv_bfloat16 *Woh = sym(g_Woh), *Wol = sym(g_Wol);
    __nv_bfloat16 *W1h = sym(g_W1h), *W1l = sym(g_W1l);
    __nv_bfloat16 *W2h = sym(g_W2h), *W2l = sym(g_W2l);
    __nv_bfloat16 *qh = sym(g_qh), *ql = sym(g_ql);
    __nv_bfloat16 *kh = sym(g_kh), *kl = sym(g_kl);
    __nv_bfloat16 *vh = sym(g_vh), *vl = sym(g_vl);
    __nv_bfloat16 *ch = sym(g_ch), *cl = sym(g_cl);
    __nv_bfloat16 *h1h = sym(g_h1h), *h1l = sym(g_h1l);
    __nv_bfloat16 *fh = sym(g_fh), *fl = sym(g_fl);
    __nv_bfloat16 *Ph = sym(g_Ph), *Pl = sym(g_Pl);
    float *S = sym(g_S), *hsa = sym(g_hsa), *h1 = sym(g_h1), *hf = sym(g_hf);
    float *rq = sym(g_rq), *rk = sym(g_rk);

    // 0) splits of inputs/weights
    split(h,  hh,  hl,  (long long)BL_ * D_);
    split(Wq, Wqh, Wql, (long long)D_ * D_);
    split(Wk, Wkh, Wkl, (long long)D_ * D_);
    split(Wv, Wvh, Wvl, (long long)D_ * D_);
    split(Wo, Woh, Wol, (long long)D_ * D_);
    split(W1, W1h, W1l, (long long)D_ * FFN_);
    split(W2, W2h, W2l, (long long)FFN_ * D_);

    // 1) Q/K/V projections -> bf16 splits directly
    gemm(hh, hl, Wqh, Wql, nullptr, nullptr, qh, ql, BL_, D_, D_, D_, D_, D_, 0, 0, 0, 1, 1.f, 0, 0);
    gemm(hh, hl, Wkh, Wkl, nullptr, nullptr, kh, kl, BL_, D_, D_, D_, D_, D_, 0, 0, 0, 1, 1.f, 0, 0);
    gemm(hh, hl, Wvh, Wvl, nullptr, nullptr, vh, vl, BL_, D_, D_, D_, D_, D_, 0, 0, 0, 1, 1.f, 0, 0);

    // 2) rank-4 relative projections
    rproj_kernel<<<BL_ / 256, 256>>>(rh, Wrq, Wrk, rq, rk);

    // 3) scores (fp32 out): per (b,head), S = Q[2048x128] @ K-as-[128x2048] / sqrt(HD)
    gemm(qh, ql, kh, kl, nullptr, S, nullptr, nullptr, L_, L_, HD_, HD_, L_, L_,
         CHUNK_, CHUNK_, (long long)L_ * L_, B_ * NH_, RSQRT_HD, 0, 0);

    // 4) fused rel-bias + softmax -> P hi/lo bf16
    {
        dim3 grid(L_, NH_, B_);
        softmax_bias_kernel<<<grid, 256>>>(S, rq, rk, Ph, Pl);
    }

    // 5) context: P[2048x2048] @ V[2048x128] -> ctx splits
    gemm(Ph, Pl, vh, vl, nullptr, nullptr, ch, cl, L_, HD_, L_, L_, HD_, HD_,
         (long long)L_ * L_, CHUNK_, CHUNK_, B_ * NH_, 1.f, 0, 0);

    // 6) output projection -> hsa fp32
    gemm(ch, cl, Woh, Wol, nullptr, hsa, nullptr, nullptr, BL_, D_, D_, D_, D_, D_, 0, 0, 0, 1, 1.f, 0, 0);

    // 7) h1 = LN(hsa + h), emit fp32 + splits
    add_ln_kernel<<<BL_, 256>>>(hsa, h, g1, be1, h1, h1h, h1l);

    // 8) FFN up: relu(h1 @ W1 + b1) -> splits
    gemm(h1h, h1l, W1h, W1l, b1, nullptr, fh, fl, BL_, FFN_, D_, D_, FFN_, FFN_, 0, 0, 0, 1, 1.f, 1, 1);

    // 9) FFN down: ffn @ W2 + b2 -> hf fp32
    gemm(fh, fl, W2h, W2l, b2, hf, nullptr, nullptr, BL_, D_, FFN_, FFN_, D_, D_, 0, 0, 0, 1, 1.f, 1, 0);

    // 10) h2 = LN(h1 + hf) -> out
    add_ln_kernel<<<BL_, 256>>>(h1, hf, g2, be2, out, nullptr, nullptr);
}

// round 9
// speedup vs baseline: 2.6292x; 1.2835x over previous
#include <cuda_runtime.h>
#include <cuda_fp16.h>
#include <math.h>

#define B_    2
#define L_    2048
#define D_    1024
#define FFN_  4096
#define NH_   8
#define HD_   128
#define BL_   (B_ * L_)
#define CHUNK_ ((long long)L_ * HD_)
#define LN_EPS 1e-5f
#define RSQRT_HD 0.08838834764831845f

// ---- GEMM tiling ----
#define BM 128
#define BN 128
#define BK 32
#define STAGES 4
#define APITCH 40                       // halfs per A smem row (80B, conflict-free)
#define BPITCH 136                      // halfs per B smem row (272B, conflict-free)
#define A_PL_B (BM * APITCH * 2)        // 10240 bytes
#define B_PL_B (BK * BPITCH * 2)        // 8704 bytes
#define STAGE_B (2 * A_PL_B + 2 * B_PL_B)   // 37888 bytes (Ah, Al, Bh, Bl)
#define OFF_AH 0
#define OFF_AL A_PL_B
#define OFF_BH (2 * A_PL_B)
#define OFF_BL (2 * A_PL_B + B_PL_B)
#define SMEM_TOTAL (STAGES * STAGE_B)       // 151552 bytes

// ---------------- scratch (device globals: allocation-free) ----------------
__device__ __align__(16) __half g_hh [BL_ * D_],  g_hl [BL_ * D_];
__device__ __align__(16) __half g_Wqh[D_ * D_],   g_Wql[D_ * D_];
__device__ __align__(16) __half g_Wkh[D_ * D_],   g_Wkl[D_ * D_];
__device__ __align__(16) __half g_Wvh[D_ * D_],   g_Wvl[D_ * D_];
__device__ __align__(16) __half g_Woh[D_ * D_],   g_Wol[D_ * D_];
__device__ __align__(16) __half g_W1h[(size_t)D_ * FFN_];
__device__ __align__(16) __half g_W2h[(size_t)FFN_ * D_];
__device__ __align__(16) __half g_qh [BL_ * D_],  g_ql [BL_ * D_];
__device__ __align__(16) __half g_kh [BL_ * D_],  g_kl [BL_ * D_];
__device__ __align__(16) __half g_vh [BL_ * D_],  g_vl [BL_ * D_];
__device__ __align__(16) __half g_ch [BL_ * D_],  g_cl [BL_ * D_];
__device__ __align__(16) __half g_h1h[BL_ * D_];
__device__ __align__(16) __half g_fh [(size_t)BL_ * FFN_];
__device__ __align__(16) __half g_Ph [(size_t)B_ * NH_ * L_ * L_];
__device__ __align__(16) __half g_Pl [(size_t)B_ * NH_ * L_ * L_];
__device__ float g_S  [(size_t)B_ * NH_ * L_ * L_];
__device__ float g_hsa[BL_ * D_];
__device__ float g_h1 [BL_ * D_];
__device__ float g_hf [BL_ * D_];
__device__ float g_rq [BL_ * 4];
__device__ float g_rk [BL_ * 4];

// ---------------- helpers ----------------
__device__ __forceinline__ void splith(float x, __half& h, __half& l)
{
    h = __float2half_rn(x);
    l = __float2half_rn(x - __half2float(h));
}

#define LDSM4(R, addr) asm volatile( \
    "ldmatrix.sync.aligned.m8n8.x4.shared.b16 {%0,%1,%2,%3}, [%4];" \
    : "=r"((R)[0]), "=r"((R)[1]), "=r"((R)[2]), "=r"((R)[3]) : "r"(addr))

#define LDSM4T(R, addr) asm volatile( \
    "ldmatrix.sync.aligned.m8n8.x4.trans.shared.b16 {%0,%1,%2,%3}, [%4];" \
    : "=r"((R)[0]), "=r"((R)[1]), "=r"((R)[2]), "=r"((R)[3]) : "r"(addr))

#define MMA16816(AC, A, B0, B1) asm volatile( \
    "mma.sync.aligned.m16n8k16.row.col.f32.f16.f16.f32 " \
    "{%0,%1,%2,%3},{%4,%5,%6,%7},{%8,%9},{%0,%1,%2,%3};" \
    : "+f"((AC)[0]), "+f"((AC)[1]), "+f"((AC)[2]), "+f"((AC)[3]) \
    : "r"((A)[0]), "r"((A)[1]), "r"((A)[2]), "r"((A)[3]), "r"(B0), "r"(B1))

#define CPA16(dst, src) asm volatile( \
    "cp.async.cg.shared.global [%0], [%1], 16;" :: "r"(dst), "l"(src))

// ---------------- fp16-split tensor-core GEMM ----------------
// C = op(alpha * A@B + bias). 3-term split if Al/Bl given, else plain fp16.
// A: [M,K] row-major (lda). B: [K,N] row-major (ldb). M%128==0, N%128==0, K%32==0.
__global__ __launch_bounds__(256, 1)
void gemm_f16_kernel(const __half* __restrict__ Ah, const __half* __restrict__ Al,
                     const __half* __restrict__ Bh, const __half* __restrict__ Bl,
                     const float* __restrict__ bias,
                     float* __restrict__ Cf, __half* __restrict__ Ch,
                     __half* __restrict__ Cl,
                     int K, int lda, int ldb, int ldc,
                     long long sA, long long sB, long long sC,
                     float alpha, int doBias, int doRelu)
{
    extern __shared__ char smem[];
    const unsigned smemS = (unsigned)__cvta_generic_to_shared(smem);
    const int tid = threadIdx.x, lane = tid & 31, w = tid >> 5;
    const int nlo = (Al != nullptr);

    const int bz = blockIdx.z;
    const int rowTile = blockIdx.y * BM, colTile = blockIdx.x * BN;
    const __half* pAh = Ah + (long long)bz * sA + (long long)rowTile * lda;
    const __half* pAl = nlo ? (Al + (long long)bz * sA + (long long)rowTile * lda) : pAh;
    const __half* pBh = Bh + (long long)bz * sB + colTile;
    const __half* pBl = nlo ? (Bl + (long long)bz * sB + colTile) : pBh;
    const long long cOff = (long long)bz * sC;

    const int wRow = (w >> 2) * 64, wCol = (w & 3) * 32;

    // loader mapping: A 512 chunks (row u>>2, 16B piece u&3); B 512 chunks (row u>>4, piece u&15)
    const int aR0 = tid >> 2,  aP0 = tid & 3;     // + u=tid+256 -> row +64
    const int bR0 = tid >> 4,  bP0 = tid & 15;    // + u=tid+256 -> row +16

    const int nT = K / BK;

    // ---- stage loader ----
    auto load_stage = [&](int slot, int k0) {
        const unsigned base = smemS + (unsigned)slot * STAGE_B;
#pragma unroll
        for (int i = 0; i < 2; i++) {
            const int ar = aR0 + i * 64;
            const unsigned aOff = (unsigned)(ar * (APITCH * 2) + aP0 * 16);
            const __half* ga = pAh + (long long)ar * lda + k0 + aP0 * 8;
            CPA16(base + OFF_AH + aOff, ga);
            if (nlo) {
                const __half* gal = pAl + (long long)ar * lda + k0 + aP0 * 8;
                CPA16(base + OFF_AL + aOff, gal);
            }
            const int br = bR0 + i * 16;
            const unsigned bOff = (unsigned)(br * (BPITCH * 2) + bP0 * 16);
            const __half* gb = pBh + (long long)(k0 + br) * ldb + bP0 * 8;
            CPA16(base + OFF_BH + bOff, gb);
            if (nlo) {
                const __half* gbl = pBl + (long long)(k0 + br) * ldb + bP0 * 8;
                CPA16(base + OFF_BL + bOff, gbl);
            }
        }
        asm volatile("cp.async.commit_group;");
    };

    // ldmatrix lane offsets
    const int aLR = lane & 15, aLC = (lane >> 4) * 8;
    const int bLR = ((lane >> 3) & 1) * 8 + (lane & 7);
    const int bLC = (lane >> 4) * 8;

    float acc[4][4][4];
#pragma unroll
    for (int i = 0; i < 4; i++)
#pragma unroll
        for (int j = 0; j < 4; j++)
#pragma unroll
            for (int e = 0; e < 4; e++) acc[i][j][e] = 0.f;

    // prologue: stages 0..2 (clamped for short K)
    load_stage(0, 0);
    load_stage(1, (1 < nT ? 1 : nT - 1) * BK);
    load_stage(2, (2 < nT ? 2 : nT - 1) * BK);

    for (int t = 0; t < nT; ++t) {
        asm volatile("cp.async.wait_group 2;" ::: "memory");
        __syncthreads();
        // issue stage t+3 (clamped; uniform group count)
        {
            const int s = t + 3;
            load_stage((t + 3) & (STAGES - 1), (s < nT ? s : nT - 1) * BK);
        }
        // compute stage t
        const unsigned sb = smemS + (unsigned)(t & (STAGES - 1)) * STAGE_B;
#pragma unroll
        for (int kk = 0; kk < 2; kk++) {
            unsigned ah[4][4], al[4][4], bh[2][4], bl[2][4];
#pragma unroll
            for (int mi = 0; mi < 4; mi++) {
                unsigned adr = sb + OFF_AH +
                    (unsigned)(((wRow + mi * 16 + aLR) * APITCH + kk * 16 + aLC) << 1);
                LDSM4(ah[mi], adr);
            }
#pragma unroll
            for (int np = 0; np < 2; np++) {
                unsigned adr = sb + OFF_BH +
                    (unsigned)(((kk * 16 + bLR) * BPITCH + wCol + np * 16 + bLC) << 1);
                LDSM4T(bh[np], adr);
            }
#pragma unroll
            for (int mi = 0; mi < 4; mi++)
#pragma unroll
                for (int ni = 0; ni < 4; ni++)
                    MMA16816(acc[mi][ni], ah[mi], bh[ni >> 1][(ni & 1) * 2], bh[ni >> 1][(ni & 1) * 2 + 1]);

            if (nlo) {
#pragma unroll
                for (int mi = 0; mi < 4; mi++) {
                    unsigned adr = sb + OFF_AL +
                        (unsigned)(((wRow + mi * 16 + aLR) * APITCH + kk * 16 + aLC) << 1);
                    LDSM4(al[mi], adr);
                }
#pragma unroll
                for (int mi = 0; mi < 4; mi++)
#pragma unroll
                    for (int ni = 0; ni < 4; ni++)
                        MMA16816(acc[mi][ni], al[mi], bh[ni >> 1][(ni & 1) * 2], bh[ni >> 1][(ni & 1) * 2 + 1]);

#pragma unroll
                for (int np = 0; np < 2; np++) {
                    unsigned adr = sb + OFF_BL +
                        (unsigned)(((kk * 16 + bLR) * BPITCH + wCol + np * 16 + bLC) << 1);
                    LDSM4T(bl[np], adr);
                }
#pragma unroll
                for (int mi = 0; mi < 4; mi++)
#pragma unroll
                    for (int ni = 0; ni < 4; ni++)
                        MMA16816(acc[mi][ni], ah[mi], bl[ni >> 1][(ni & 1) * 2], bl[ni >> 1][(ni & 1) * 2 + 1]);
            }
        }
    }

    // epilogue
#pragma unroll
    for (int mi = 0; mi < 4; mi++)
#pragma unroll
        for (int ni = 0; ni < 4; ni++) {
            const int r0 = rowTile + wRow + mi * 16 + (lane >> 2);
            const int c  = colTile + wCol + ni * 8 + (lane & 3) * 2;
            float* a = acc[mi][ni];
#pragma unroll
            for (int hrow = 0; hrow < 2; hrow++) {
                const int r = r0 + hrow * 8;
                float o0 = alpha * a[hrow * 2 + 0];
                float o1 = alpha * a[hrow * 2 + 1];
                if (doBias) { o0 += bias[c]; o1 += bias[c + 1]; }
                if (doRelu) { o0 = fmaxf(o0, 0.f); o1 = fmaxf(o1, 0.f); }
                const long long idx = cOff + (long long)r * ldc + c;
                if (Cf) {
                    *(float2*)&Cf[idx] = make_float2(o0, o1);
                } else {
                    __half h0, l0, h1, l1;
                    splith(o0, h0, l0); splith(o1, h1, l1);
                    __half2 ph; ph.x = h0; ph.y = h1;
                    *(__half2*)&Ch[idx] = ph;
                    if (Cl) {
                        __half2 pl; pl.x = l0; pl.y = l1;
                        *(__half2*)&Cl[idx] = pl;
                    }
                }
            }
        }
}

// ---------------- fp32 -> fp16 hi(/lo) split ----------------
__global__ __launch_bounds__(256)
void split_kernel(const float* __restrict__ src, __half* __restrict__ hi,
                  __half* __restrict__ lo, long long n)
{
    const long long i = ((long long)blockIdx.x * 256 + threadIdx.x) * 4;
    if (i >= n) return;
    float4 v = *(const float4*)(src + i);
    __half h0, l0, h1, l1, h2, l2, h3, l3;
    splith(v.x, h0, l0); splith(v.y, h1, l1);
    splith(v.z, h2, l2); splith(v.w, h3, l3);
    __half2 a, b;
    a.x = h0; a.y = h1; b.x = h2; b.y = h3;
    *(__half2*)&hi[i] = a; *(__half2*)&hi[i + 2] = b;
    if (lo) {
        a.x = l0; a.y = l1; b.x = l2; b.y = l3;
        *(__half2*)&lo[i] = a; *(__half2*)&lo[i + 2] = b;
    }
}

// ---------------- rank-4 relative projections ----------------
__global__ void rproj_kernel(const float* __restrict__ rh,
                             const float* __restrict__ Wrq,
                             const float* __restrict__ Wrk,
                             float* __restrict__ rq, float* __restrict__ rk)
{
    const int i = blockIdx.x * blockDim.x + threadIdx.x;
    if (i >= BL_) return;
    const float h0 = rh[i * 4 + 0], h1v = rh[i * 4 + 1];
    const float h2 = rh[i * 4 + 2], h3 = rh[i * 4 + 3];
#pragma unroll
    for (int r = 0; r < 4; r++) {
        rq[i * 4 + r] = h0 * Wrq[r] + h1v * Wrq[4 + r] + h2 * Wrq[8 + r] + h3 * Wrq[12 + r];
        rk[i * 4 + r] = h0 * Wrk[r] + h1v * Wrk[4 + r] + h2 * Wrk[8 + r] + h3 * Wrk[12 + r];
    }
}

// ---------------- block reduction ----------------
__device__ __forceinline__ float blockReduce(float v, float* red, bool isMax)
{
    __syncthreads();
#pragma unroll
    for (int o = 16; o > 0; o >>= 1) {
        float t = __shfl_xor_sync(0xffffffffu, v, o);
        v = isMax ? fmaxf(v, t) : (v + t);
    }
    const int warp = threadIdx.x >> 5, lane = threadIdx.x & 31;
    if (lane == 0) red[warp] = v;
    __syncthreads();
    if (warp == 0) {
        v = (lane < 8) ? red[lane] : (isMax ? -INFINITY : 0.f);
#pragma unroll
        for (int o = 4; o > 0; o >>= 1) {
            float t = __shfl_xor_sync(0xffffffffu, v, o);
            v = isMax ? fmaxf(v, t) : (v + t);
        }
        if (lane == 0) red[0] = v;
    }
    __syncthreads();
    return red[0];
}

// ---------------- fused rel-bias + softmax -> fp16 hi/lo ----------------
__global__ __launch_bounds__(256)
void softmax_bias_kernel(const float* __restrict__ S,
                         const float* __restrict__ rq,
                         const float* __restrict__ rk,
                         __half* __restrict__ Ph,
                         __half* __restrict__ Pl)
{
    __shared__ float red[32];
    const int l = blockIdx.x, n = blockIdx.y, b = blockIdx.z;
    const long long rowOff = ((((long long)b * NH_ + n) * L_) + l) * L_;
    const float* row = S + rowOff;
    const float* rqp = rq + ((long long)b * L_ + l) * 4;
    const float* rkp = rk + (long long)b * L_ * 4;
    const float q0 = rqp[0] * 0.5f, q1 = rqp[1] * 0.5f;
    const float q2 = rqp[2] * 0.5f, q3 = rqp[3] * 0.5f;
    const int tid = threadIdx.x;

    float vals[8];
    float vmax = -INFINITY;
#pragma unroll
    for (int j = 0; j < 8; j++) {
        const int m = j * 256 + tid;
        const float bias = q0 * rkp[m] + q1 * rkp[L_ + m]
                         + q2 * rkp[2 * L_ + m] + q3 * rkp[3 * L_ + m];
        const float v = row[m] + bias;
        vals[j] = v;
        vmax = fmaxf(vmax, v);
    }
    vmax = blockReduce(vmax, red, true);

    float sum = 0.f;
#pragma unroll
    for (int j = 0; j < 8; j++) {
        vals[j] = __expf(vals[j] - vmax);
        sum += vals[j];
    }
    sum = blockReduce(sum, red, false);
    const float inv = 1.f / sum;
#pragma unroll
    for (int j = 0; j < 8; j++) {
        const float p = vals[j] * inv;
        __half h, lo;
        splith(p, h, lo);
        Ph[rowOff + j * 256 + tid] = h;
        Pl[rowOff + j * 256 + tid] = lo;
    }
}

// ---------------- fused residual-add + LayerNorm (+ optional fp16 out) -----
__global__ __launch_bounds__(256)
void add_ln_kernel(const float* __restrict__ x, const float* __restrict__ y,
                   const float* __restrict__ g, const float* __restrict__ be,
                   float* __restrict__ outF, __half* __restrict__ outH)
{
    __shared__ float red[32];
    const long long row = blockIdx.x;
    const float* xp = x + row * D_;
    const float* yp = y + row * D_;
    const int tid = threadIdx.x;

    float v[4];
    float s = 0.f;
#pragma unroll
    for (int j = 0; j < 4; j++) {
        const int i = j * 256 + tid;
        v[j] = xp[i] + yp[i];
        s += v[j];
    }
    const float mean = blockReduce(s, red, false) * (1.f / D_);

    float sq = 0.f;
#pragma unroll
    for (int j = 0; j < 4; j++) {
        const float d = v[j] - mean;
        sq += d * d;
    }
    const float var = blockReduce(sq, red, false) * (1.f / D_);
    const float rstd = rsqrtf(var + LN_EPS);
#pragma unroll
    for (int j = 0; j < 4; j++) {
        const int i = j * 256 + tid;
        const float o = (v[j] - mean) * rstd * g[i] + be[i];
        outF[row * D_ + i] = o;
        if (outH) outH[row * D_ + i] = __float2half_rn(o);
    }
}

// ---------------- host helpers ----------------
static void gemm(const __half* Ah, const __half* Al,
                 const __half* Bh, const __half* Bl,
                 const float* bias, float* Cf, __half* Ch, __half* Cl,
                 int M, int N, int K, int lda, int ldb, int ldc,
                 long long sA, long long sB, long long sC, int batch,
                 float alpha, int doBias, int doRelu)
{
    dim3 grid(N / BN, M / BM, batch), block(256);
    gemm_f16_kernel<<<grid, block, SMEM_TOTAL>>>(Ah, Al, Bh, Bl, bias, Cf, Ch, Cl,
                                                 K, lda, ldb, ldc, sA, sB, sC,
                                                 alpha, doBias, doRelu);
}

static void split(const float* src, __half* hi, __half* lo, long long n)
{
    split_kernel<<<(int)(n / 1024), 256>>>(src, hi, lo, n);
}

template <typename T>
static T* sym(T* symbol) { void* p; cudaGetSymbolAddress(&p, (const void*)symbol); return (T*)p; }

extern "C" void kernel_launch(void* const* d_in, const int* in_sizes, int n_in,
                              void* d_out, int out_size)
{
    const float* h   = (const float*)d_in[0];
    const float* rh  = (const float*)d_in[1];
    const float* Wq  = (const float*)d_in[2];
    const float* Wk  = (const float*)d_in[3];
    const float* Wv  = (const float*)d_in[4];
    const float* Wo  = (const float*)d_in[5];
    const float* Wrk = (const float*)d_in[6];
    const float* Wrq = (const float*)d_in[7];
    const float* W1  = (const float*)d_in[8];
    const float* b1  = (const float*)d_in[9];
    const float* W2  = (const float*)d_in[10];
    const float* b2  = (const float*)d_in[11];
    const float* g1  = (const float*)d_in[12];
    const float* be1 = (const float*)d_in[13];
    const float* g2  = (const float*)d_in[14];
    const float* be2 = (const float*)d_in[15];
    float* out = (float*)d_out;

    cudaFuncSetAttribute(gemm_f16_kernel,
                         cudaFuncAttributeMaxDynamicSharedMemorySize, SMEM_TOTAL);

    __half *hh = sym(g_hh), *hl = sym(g_hl);
    __half *Wqh = sym(g_Wqh), *Wql = sym(g_Wql);
    __half *Wkh = sym(g_Wkh), *Wkl = sym(g_Wkl);
    __half *Wvh = sym(g_Wvh), *Wvl = sym(g_Wvl);
    __half *Woh = sym(g_Woh), *Wol = sym(g_Wol);
    __half *W1h = sym(g_W1h), *W2h = sym(g_W2h);
    __half *qh = sym(g_qh), *ql = sym(g_ql);
    __half *kh = sym(g_kh), *kl = sym(g_kl);
    __half *vh = sym(g_vh), *vl = sym(g_vl);
    __half *ch = sym(g_ch), *cl = sym(g_cl);
    __half *h1h = sym(g_h1h);
    __half *fh = sym(g_fh);
    __half *Ph = sym(g_Ph), *Pl = sym(g_Pl);
    float *S = sym(g_S), *hsa = sym(g_hsa), *h1 = sym(g_h1), *hf = sym(g_hf);
    float *rq = sym(g_rq), *rk = sym(g_rk);

    // 0-3) weight splits (attention path, hi+lo)
    split(Wq, Wqh, Wql, (long long)D_ * D_);
    split(Wk, Wkh, Wkl, (long long)D_ * D_);
    split(Wv, Wvh, Wvl, (long long)D_ * D_);
    split(Wo, Woh, Wol, (long long)D_ * D_);
    // 4) input split
    split(h, hh, hl, (long long)BL_ * D_);
    // 5-7) QKV projections, 3-term (launch #5 is the profiled GEMM)
    gemm(hh, hl, Wqh, Wql, nullptr, nullptr, qh, ql, BL_, D_, D_, D_, D_, D_, 0, 0, 0, 1, 1.f, 0, 0);
    gemm(hh, hl, Wkh, Wkl, nullptr, nullptr, kh, kl, BL_, D_, D_, D_, D_, D_, 0, 0, 0, 1, 1.f, 0, 0);
    gemm(hh, hl, Wvh, Wvl, nullptr, nullptr, vh, vl, BL_, D_, D_, D_, D_, D_, 0, 0, 0, 1, 1.f, 0, 0);
    // 8) rank-4 projections
    rproj_kernel<<<BL_ / 256, 256>>>(rh, Wrq, Wrk, rq, rk);
    // 9-10) FFN weights, single-term fp16
    split(W1, W1h, nullptr, (long long)D_ * FFN_);
    split(W2, W2h, nullptr, (long long)FFN_ * D_);
    // 11) scores: per (b,head) chunk, S = Q[2048x128] @ Kt[128x2048] / sqrt(HD)  (3-term)
    gemm(qh, ql, kh, kl, nullptr, S, nullptr, nullptr, L_, L_, HD_, HD_, L_, L_,
         CHUNK_, CHUNK_, (long long)L_ * L_, B_ * NH_, RSQRT_HD, 0, 0);
    // 12) fused rel-bias + softmax -> P hi/lo
    {
        dim3 grid(L_, NH_, B_);
        softmax_bias_kernel<<<grid, 256>>>(S, rq, rk, Ph, Pl);
    }
    // 13) context: P[2048x2048] @ V[2048x128]  (3-term)
    gemm(Ph, Pl, vh, vl, nullptr, nullptr, ch, cl, L_, HD_, L_, L_, HD_, HD_,
         (long long)L_ * L_, CHUNK_, CHUNK_, B_ * NH_, 1.f, 0, 0);
    // 14) output projection  (3-term)
    gemm(ch, cl, Woh, Wol, nullptr, hsa, nullptr, nullptr, BL_, D_, D_, D_, D_, D_, 0, 0, 0, 1, 1.f, 0, 0);
    // 15) h1 = LN(hsa + h)
    add_ln_kernel<<<BL_, 256>>>(hsa, h, g1, be1, h1, h1h);
    // 16) FFN up: relu(h1 @ W1 + b1)  (single-term fp16)
    gemm(h1h, nullptr, W1h, nullptr, b1, nullptr, fh, nullptr, BL_, FFN_, D_, D_, FFN_, FFN_, 0, 0, 0, 1, 1.f, 1, 1);
    // 17) FFN down: ffn @ W2 + b2  (single-term fp16)
    gemm(fh, nullptr, W2h, nullptr, b2, hf, nullptr, nullptr, BL_, D_, FFN_, FFN_, D_, D_, 0, 0, 0, 1, 1.f, 1, 0);
    // 18) h2 = LN(h1 + hf) -> out
    add_ln_kernel<<<BL_, 256>>>(h1, hf, g2, be2, out, nullptr);
}

// round 11
// speedup vs baseline: 2.9490x; 1.1216x over previous
#include <cuda_runtime.h>
#include <cuda_fp16.h>
#include <math.h>

#define B_    2
#define L_    2048
#define D_    1024
#define FFN_  4096
#define NH_   8
#define HD_   128
#define BL_   (B_ * L_)
#define CHUNK_ ((long long)L_ * HD_)
#define LN_EPS 1e-5f
#define RSQRT_HD 0.08838834764831845f

// ---- GEMM tiling (single-term fp16) ----
#define BM 128
#define BN 128
#define BK 32
#define STAGES 4
#define APITCH 40                       // halfs per A smem row (80B, conflict-free)
#define BPITCH 136                      // halfs per B smem row (272B, conflict-free)
#define A_PL_B (BM * APITCH * 2)        // 10240 bytes
#define B_PL_B (BK * BPITCH * 2)        // 8704 bytes
#define STAGE_B (A_PL_B + B_PL_B)       // 18944 bytes
#define OFF_B A_PL_B
#define SMEM_TOTAL (STAGES * STAGE_B)   // 75776 bytes -> 2 CTAs/SM

// ---------------- scratch (device globals: allocation-free) ----------------
__device__ __align__(16) __half g_hh [BL_ * D_];
__device__ __align__(16) __half g_Wqh[D_ * D_];
__device__ __align__(16) __half g_Wkh[D_ * D_];
__device__ __align__(16) __half g_Wvh[D_ * D_];
__device__ __align__(16) __half g_Woh[D_ * D_];
__device__ __align__(16) __half g_W1h[(size_t)D_ * FFN_];
__device__ __align__(16) __half g_W2h[(size_t)FFN_ * D_];
__device__ __align__(16) __half g_qh [BL_ * D_];
__device__ __align__(16) __half g_kh [BL_ * D_];
__device__ __align__(16) __half g_vh [BL_ * D_];
__device__ __align__(16) __half g_ch [BL_ * D_];
__device__ __align__(16) __half g_h1h[BL_ * D_];
__device__ __align__(16) __half g_fh [(size_t)BL_ * FFN_];
__device__ __align__(16) __half g_Ph [(size_t)B_ * NH_ * L_ * L_];
__device__ float g_S  [(size_t)B_ * NH_ * L_ * L_];
__device__ float g_hsa[BL_ * D_];
__device__ float g_h1 [BL_ * D_];
__device__ float g_hf [BL_ * D_];
__device__ float g_rq [BL_ * 4];
__device__ float g_rk [BL_ * 4];

// ---------------- asm helpers ----------------
#define LDSM4(R, addr) asm volatile( \
    "ldmatrix.sync.aligned.m8n8.x4.shared.b16 {%0,%1,%2,%3}, [%4];" \
    : "=r"((R)[0]), "=r"((R)[1]), "=r"((R)[2]), "=r"((R)[3]) : "r"(addr))

#define LDSM4T(R, addr) asm volatile( \
    "ldmatrix.sync.aligned.m8n8.x4.trans.shared.b16 {%0,%1,%2,%3}, [%4];" \
    : "=r"((R)[0]), "=r"((R)[1]), "=r"((R)[2]), "=r"((R)[3]) : "r"(addr))

#define MMA16816(AC, A, B0, B1) asm volatile( \
    "mma.sync.aligned.m16n8k16.row.col.f32.f16.f16.f32 " \
    "{%0,%1,%2,%3},{%4,%5,%6,%7},{%8,%9},{%0,%1,%2,%3};" \
    : "+f"((AC)[0]), "+f"((AC)[1]), "+f"((AC)[2]), "+f"((AC)[3]) \
    : "r"((A)[0]), "r"((A)[1]), "r"((A)[2]), "r"((A)[3]), "r"(B0), "r"(B1))

#define CPA16(dst, src) asm volatile( \
    "cp.async.cg.shared.global [%0], [%1], 16;" :: "r"(dst), "l"(src))

// ---------------- single-term fp16 tensor-core GEMM ----------------
// C = op(alpha * A@B + bias). A: [M,K] row-major. B: [K,N] row-major.
// M%128==0, N%128==0, K%32==0.
__global__ __launch_bounds__(256, 2)
void gemm_f16_kernel(const __half* __restrict__ Ah, const __half* __restrict__ Bh,
                     const float* __restrict__ bias,
                     float* __restrict__ Cf, __half* __restrict__ Ch,
                     int K, int lda, int ldb, int ldc,
                     long long sA, long long sB, long long sC,
                     float alpha, int doBias, int doRelu)
{
    extern __shared__ char smem[];
    const unsigned smemS = (unsigned)__cvta_generic_to_shared(smem);
    const int tid = threadIdx.x, lane = tid & 31, w = tid >> 5;

    const int bz = blockIdx.z;
    const int rowTile = blockIdx.y * BM, colTile = blockIdx.x * BN;
    const __half* pA = Ah + (long long)bz * sA + (long long)rowTile * lda;
    const __half* pB = Bh + (long long)bz * sB + colTile;
    const long long cOff = (long long)bz * sC;

    const int wRow = (w >> 2) * 64, wCol = (w & 3) * 32;

    // loader: A 512x16B chunks (row u>>2, piece u&3); B 512 chunks (row u>>4, piece u&15)
    const int aR0 = tid >> 2,  aP0 = tid & 3;     // chunk tid and tid+256 (row +64)
    const int bR0 = tid >> 4,  bP0 = tid & 15;    // chunk tid and tid+256 (row +16)

    const int nT = K / BK;

    auto load_stage = [&](int slot, int k0) {
        const unsigned base = smemS + (unsigned)slot * STAGE_B;
#pragma unroll
        for (int i = 0; i < 2; i++) {
            const int ar = aR0 + i * 64;
            CPA16(base + (unsigned)(ar * (APITCH * 2) + aP0 * 16),
                  pA + (long long)ar * lda + k0 + aP0 * 8);
            const int br = bR0 + i * 16;
            CPA16(base + OFF_B + (unsigned)(br * (BPITCH * 2) + bP0 * 16),
                  pB + (long long)(k0 + br) * ldb + bP0 * 8);
        }
        asm volatile("cp.async.commit_group;");
    };

    // ldmatrix lane offsets
    const int aLR = lane & 15, aLC = (lane >> 4) * 8;
    const int bLR = ((lane >> 3) & 1) * 8 + (lane & 7);
    const int bLC = (lane >> 4) * 8;

    float acc[4][4][4];
#pragma unroll
    for (int i = 0; i < 4; i++)
#pragma unroll
        for (int j = 0; j < 4; j++)
#pragma unroll
            for (int e = 0; e < 4; e++) acc[i][j][e] = 0.f;

    load_stage(0, 0);
    load_stage(1, (1 < nT ? 1 : nT - 1) * BK);
    load_stage(2, (2 < nT ? 2 : nT - 1) * BK);

    for (int t = 0; t < nT; ++t) {
        asm volatile("cp.async.wait_group 2;" ::: "memory");
        __syncthreads();
        {
            const int s = t + 3;
            load_stage((t + 3) & (STAGES - 1), (s < nT ? s : nT - 1) * BK);
        }
        const unsigned sb = smemS + (unsigned)(t & (STAGES - 1)) * STAGE_B;
#pragma unroll
        for (int kk = 0; kk < 2; kk++) {
            unsigned ah[4][4], bh[2][4];
#pragma unroll
            for (int mi = 0; mi < 4; mi++) {
                unsigned adr = sb +
                    (unsigned)(((wRow + mi * 16 + aLR) * APITCH + kk * 16 + aLC) << 1);
                LDSM4(ah[mi], adr);
            }
#pragma unroll
            for (int np = 0; np < 2; np++) {
                unsigned adr = sb + OFF_B +
                    (unsigned)(((kk * 16 + bLR) * BPITCH + wCol + np * 16 + bLC) << 1);
                LDSM4T(bh[np], adr);
            }
#pragma unroll
            for (int mi = 0; mi < 4; mi++)
#pragma unroll
                for (int ni = 0; ni < 4; ni++)
                    MMA16816(acc[mi][ni], ah[mi], bh[ni >> 1][(ni & 1) * 2], bh[ni >> 1][(ni & 1) * 2 + 1]);
        }
    }

    // epilogue
#pragma unroll
    for (int mi = 0; mi < 4; mi++)
#pragma unroll
        for (int ni = 0; ni < 4; ni++) {
            const int r0 = rowTile + wRow + mi * 16 + (lane >> 2);
            const int c  = colTile + wCol + ni * 8 + (lane & 3) * 2;
            float* a = acc[mi][ni];
#pragma unroll
            for (int hrow = 0; hrow < 2; hrow++) {
                const int r = r0 + hrow * 8;
                float o0 = alpha * a[hrow * 2 + 0];
                float o1 = alpha * a[hrow * 2 + 1];
                if (doBias) { o0 += bias[c]; o1 += bias[c + 1]; }
                if (doRelu) { o0 = fmaxf(o0, 0.f); o1 = fmaxf(o1, 0.f); }
                const long long idx = cOff + (long long)r * ldc + c;
                if (Cf) {
                    *(float2*)&Cf[idx] = make_float2(o0, o1);
                } else {
                    __half2 p; p.x = __float2half_rn(o0); p.y = __float2half_rn(o1);
                    *(__half2*)&Ch[idx] = p;
                }
            }
        }
}

// ---------------- batched fp32 -> fp16 convert (up to 4 tensors) -----------
__global__ __launch_bounds__(256)
void conv4_kernel(const float* __restrict__ s0, const float* __restrict__ s1,
                  const float* __restrict__ s2, const float* __restrict__ s3,
                  __half* __restrict__ o0, __half* __restrict__ o1,
                  __half* __restrict__ o2, __half* __restrict__ o3,
                  long long n0, long long n1, long long n2, long long n3)
{
    long long i = ((long long)blockIdx.x * 256 + threadIdx.x) * 8;
    const float* s; __half* o;
    if (i < n0)                     { s = s0; o = o0; }
    else if ((i -= n0) < n1)        { s = s1; o = o1; }
    else if ((i -= n1) < n2)        { s = s2; o = o2; }
    else if ((i -= n2) < n3)        { s = s3; o = o3; }
    else return;
    float4 v0 = *(const float4*)(s + i);
    float4 v1 = *(const float4*)(s + i + 4);
    __half2 r[4];
    r[0].x = __float2half_rn(v0.x); r[0].y = __float2half_rn(v0.y);
    r[1].x = __float2half_rn(v0.z); r[1].y = __float2half_rn(v0.w);
    r[2].x = __float2half_rn(v1.x); r[2].y = __float2half_rn(v1.y);
    r[3].x = __float2half_rn(v1.z); r[3].y = __float2half_rn(v1.w);
    *(uint4*)&o[i] = *(uint4*)r;
}

// ---------------- rank-4 relative projections ----------------
__global__ void rproj_kernel(const float* __restrict__ rh,
                             const float* __restrict__ Wrq,
                             const float* __restrict__ Wrk,
                             float* __restrict__ rq, float* __restrict__ rk)
{
    const int i = blockIdx.x * blockDim.x + threadIdx.x;
    if (i >= BL_) return;
    const float h0 = rh[i * 4 + 0], h1v = rh[i * 4 + 1];
    const float h2 = rh[i * 4 + 2], h3 = rh[i * 4 + 3];
#pragma unroll
    for (int r = 0; r < 4; r++) {
        rq[i * 4 + r] = h0 * Wrq[r] + h1v * Wrq[4 + r] + h2 * Wrq[8 + r] + h3 * Wrq[12 + r];
        rk[i * 4 + r] = h0 * Wrk[r] + h1v * Wrk[4 + r] + h2 * Wrk[8 + r] + h3 * Wrk[12 + r];
    }
}

// ---------------- block reduction ----------------
__device__ __forceinline__ float blockReduce(float v, float* red, bool isMax)
{
    __syncthreads();
#pragma unroll
    for (int o = 16; o > 0; o >>= 1) {
        float t = __shfl_xor_sync(0xffffffffu, v, o);
        v = isMax ? fmaxf(v, t) : (v + t);
    }
    const int warp = threadIdx.x >> 5, lane = threadIdx.x & 31;
    if (lane == 0) red[warp] = v;
    __syncthreads();
    if (warp == 0) {
        v = (lane < 8) ? red[lane] : (isMax ? -INFINITY : 0.f);
#pragma unroll
        for (int o = 4; o > 0; o >>= 1) {
            float t = __shfl_xor_sync(0xffffffffu, v, o);
            v = isMax ? fmaxf(v, t) : (v + t);
        }
        if (lane == 0) red[0] = v;
    }
    __syncthreads();
    return red[0];
}

// ---------------- fused rel-bias + softmax -> fp16 ----------------
__global__ __launch_bounds__(256)
void softmax_bias_kernel(const float* __restrict__ S,
                         const float* __restrict__ rq,
                         const float* __restrict__ rk,
                         __half* __restrict__ Ph)
{
    __shared__ float red[32];
    const int l = blockIdx.x, n = blockIdx.y, b = blockIdx.z;
    const long long rowOff = ((((long long)b * NH_ + n) * L_) + l) * L_;
    const float* row = S + rowOff;
    const float* rqp = rq + ((long long)b * L_ + l) * 4;
    const float* rkp = rk + (long long)b * L_ * 4;
    const float q0 = rqp[0] * 0.5f, q1 = rqp[1] * 0.5f;
    const float q2 = rqp[2] * 0.5f, q3 = rqp[3] * 0.5f;
    const int tid = threadIdx.x;

    float vals[8];
    float vmax = -INFINITY;
#pragma unroll
    for (int j = 0; j < 8; j++) {
        const int m = j * 256 + tid;
        const float bias = q0 * rkp[m] + q1 * rkp[L_ + m]
                         + q2 * rkp[2 * L_ + m] + q3 * rkp[3 * L_ + m];
        const float v = row[m] + bias;
        vals[j] = v;
        vmax = fmaxf(vmax, v);
    }
    vmax = blockReduce(vmax, red, true);

    float sum = 0.f;
#pragma unroll
    for (int j = 0; j < 8; j++) {
        vals[j] = __expf(vals[j] - vmax);
        sum += vals[j];
    }
    sum = blockReduce(sum, red, false);
    const float inv = 1.f / sum;
#pragma unroll
    for (int j = 0; j < 8; j++)
        Ph[rowOff + j * 256 + tid] = __float2half_rn(vals[j] * inv);
}

// ---------------- fused residual-add + LayerNorm (+ optional fp16 out) -----
__global__ __launch_bounds__(256)
void add_ln_kernel(const float* __restrict__ x, const float* __restrict__ y,
                   const float* __restrict__ g, const float* __restrict__ be,
                   float* __restrict__ outF, __half* __restrict__ outH)
{
    __shared__ float red[32];
    const long long row = blockIdx.x;
    const float* xp = x + row * D_;
    const float* yp = y + row * D_;
    const int tid = threadIdx.x;

    float v[4];
    float s = 0.f;
#pragma unroll
    for (int j = 0; j < 4; j++) {
        const int i = j * 256 + tid;
        v[j] = xp[i] + yp[i];
        s += v[j];
    }
    const float mean = blockReduce(s, red, false) * (1.f / D_);

    float sq = 0.f;
#pragma unroll
    for (int j = 0; j < 4; j++) {
        const float d = v[j] - mean;
        sq += d * d;
    }
    const float var = blockReduce(sq, red, false) * (1.f / D_);
    const float rstd = rsqrtf(var + LN_EPS);
#pragma unroll
    for (int j = 0; j < 4; j++) {
        const int i = j * 256 + tid;
        const float o = (v[j] - mean) * rstd * g[i] + be[i];
        outF[row * D_ + i] = o;
        if (outH) outH[row * D_ + i] = __float2half_rn(o);
    }
}

// ---------------- host helpers ----------------
static void gemm(const __half* Ah, const __half* Bh,
                 const float* bias, float* Cf, __half* Ch,
                 int M, int N, int K, int lda, int ldb, int ldc,
                 long long sA, long long sB, long long sC, int batch,
                 float alpha, int doBias, int doRelu)
{
    dim3 grid(N / BN, M / BM, batch), block(256);
    gemm_f16_kernel<<<grid, block, SMEM_TOTAL>>>(Ah, Bh, bias, Cf, Ch,
                                                 K, lda, ldb, ldc, sA, sB, sC,
                                                 alpha, doBias, doRelu);
}

template <typename T>
static T* sym(T* symbol) { void* p; cudaGetSymbolAddress(&p, (const void*)symbol); return (T*)p; }

extern "C" void kernel_launch(void* const* d_in, const int* in_sizes, int n_in,
                              void* d_out, int out_size)
{
    const float* h   = (const float*)d_in[0];
    const float* rh  = (const float*)d_in[1];
    const float* Wq  = (const float*)d_in[2];
    const float* Wk  = (const float*)d_in[3];
    const float* Wv  = (const float*)d_in[4];
    const float* Wo  = (const float*)d_in[5];
    const float* Wrk = (const float*)d_in[6];
    const float* Wrq = (const float*)d_in[7];
    const float* W1  = (const float*)d_in[8];
    const float* b1  = (const float*)d_in[9];
    const float* W2  = (const float*)d_in[10];
    const float* b2  = (const float*)d_in[11];
    const float* g1  = (const float*)d_in[12];
    const float* be1 = (const float*)d_in[13];
    const float* g2  = (const float*)d_in[14];
    const float* be2 = (const float*)d_in[15];
    float* out = (float*)d_out;

    cudaFuncSetAttribute(gemm_f16_kernel,
                         cudaFuncAttributeMaxDynamicSharedMemorySize, SMEM_TOTAL);

    __half *hh = sym(g_hh);
    __half *Wqh = sym(g_Wqh), *Wkh = sym(g_Wkh), *Wvh = sym(g_Wvh), *Woh = sym(g_Woh);
    __half *W1h = sym(g_W1h), *W2h = sym(g_W2h);
    __half *qh = sym(g_qh), *kh = sym(g_kh), *vh = sym(g_vh);
    __half *ch = sym(g_ch), *h1h = sym(g_h1h), *fh = sym(g_fh);
    __half *Ph = sym(g_Ph);
    float *S = sym(g_S), *hsa = sym(g_hsa), *h1 = sym(g_h1), *hf = sym(g_hf);
    float *rq = sym(g_rq), *rk = sym(g_rk);

    const long long nH = (long long)BL_ * D_;      // 4M
    const long long nW = (long long)D_ * D_;       // 1M
    const long long nF = (long long)D_ * FFN_;     // 4M

    // 0) convert h, Wq, Wk, Wv  (7M elems)
    conv4_kernel<<<(int)((nH + 3 * nW) / 2048), 256>>>(
        h, Wq, Wk, Wv, hh, Wqh, Wkh, Wvh, nH, nW, nW, nW);
    // 1-3) QKV projections
    gemm(hh, Wqh, nullptr, nullptr, qh, BL_, D_, D_, D_, D_, D_, 0, 0, 0, 1, 1.f, 0, 0);
    gemm(hh, Wkh, nullptr, nullptr, kh, BL_, D_, D_, D_, D_, D_, 0, 0, 0, 1, 1.f, 0, 0);
    gemm(hh, Wvh, nullptr, nullptr, vh, BL_, D_, D_, D_, D_, D_, 0, 0, 0, 1, 1.f, 0, 0);
    // 4) scores: per (b,head) chunk, S = Q[2048x128] @ Kt[128x2048] / sqrt(HD)
    gemm(qh, kh, nullptr, S, nullptr, L_, L_, HD_, HD_, L_, L_,
         CHUNK_, CHUNK_, (long long)L_ * L_, B_ * NH_, RSQRT_HD, 0, 0);
    // 5) rank-4 projections
    rproj_kernel<<<BL_ / 256, 256>>>(rh, Wrq, Wrk, rq, rk);
    // 6) convert Wo, W1, W2  (9M elems)
    conv4_kernel<<<(int)((nW + 2 * nF) / 2048), 256>>>(
        Wo, W1, W2, nullptr, Woh, W1h, W2h, nullptr, nW, nF, nF, 0);
    // 7) fused rel-bias + softmax -> P fp16
    {
        dim3 grid(L_, NH_, B_);
        softmax_bias_kernel<<<grid, 256>>>(S, rq, rk, Ph);
    }
    // 8) context: P[2048x2048] @ V[2048x128]
    gemm(Ph, vh, nullptr, nullptr, ch, L_, HD_, L_, L_, HD_, HD_,
         (long long)L_ * L_, CHUNK_, CHUNK_, B_ * NH_, 1.f, 0, 0);
    // 9) output projection
    gemm(ch, Woh, nullptr, hsa, nullptr, BL_, D_, D_, D_, D_, D_, 0, 0, 0, 1, 1.f, 0, 0);
    // 10) h1 = LN(hsa + h)
    add_ln_kernel<<<BL_, 256>>>(hsa, h, g1, be1, h1, h1h);
    // 11) FFN up: relu(h1 @ W1 + b1)
    gemm(h1h, W1h, b1, nullptr, fh, BL_, FFN_, D_, D_, FFN_, FFN_, 0, 0, 0, 1, 1.f, 1, 1);
    // 12) FFN down: ffn @ W2 + b2
    gemm(fh, W2h, b2, hf, nullptr, BL_, D_, FFN_, FFN_, D_, D_, 0, 0, 0, 1, 1.f, 1, 0);
    // 13) h2 = LN(h1 + hf) -> out
    add_ln_kernel<<<BL_, 256>>>(h1, hf, g2, be2, out, nullptr);
}

// round 12
// speedup vs baseline: 4.3567x; 1.4773x over previous
#include <cuda_runtime.h>
#include <cuda_fp16.h>
#include <math.h>

#define B_    2
#define L_    2048
#define D_    1024
#define FFN_  4096
#define NH_   8
#define HD_   128
#define BL_   (B_ * L_)
#define CHUNK_ ((long long)L_ * HD_)
#define LN_EPS 1e-5f
#define RSQRT_HD 0.08838834764831845f

// ---- GEMM tiling ----
#define BM 128
#define BK 32
#define STAGES 4
#define APITCH 40                          // halfs per A smem row
#define A_PL_B (BM * APITCH * 2)           // 10240 bytes

// ---------------- scratch (device globals: allocation-free) ----------------
__device__ __align__(16) __half g_hh [BL_ * D_];
__device__ __align__(16) __half g_Wqh[D_ * D_];
__device__ __align__(16) __half g_Wkh[D_ * D_];
__device__ __align__(16) __half g_Wvh[D_ * D_];
__device__ __align__(16) __half g_Woh[D_ * D_];
__device__ __align__(16) __half g_W1h[(size_t)D_ * FFN_];
__device__ __align__(16) __half g_W2h[(size_t)FFN_ * D_];
__device__ __align__(16) __half g_qh [BL_ * D_];
__device__ __align__(16) __half g_kh [BL_ * D_];
__device__ __align__(16) __half g_vh [BL_ * D_];
__device__ __align__(16) __half g_ch [BL_ * D_];
__device__ __align__(16) __half g_h1h[BL_ * D_];
__device__ __align__(16) __half g_fh [(size_t)BL_ * FFN_];
__device__ __align__(16) __half g_Ph [(size_t)B_ * NH_ * L_ * L_];
__device__ float g_S  [(size_t)B_ * NH_ * L_ * L_];
__device__ float g_hsa[BL_ * D_];
__device__ float g_h1 [BL_ * D_];
__device__ float g_hf [BL_ * D_];
__device__ float g_rq [BL_ * 4];
__device__ float g_rk [BL_ * 4];

// ---------------- asm helpers ----------------
#define LDSM4(R, addr) asm volatile( \
    "ldmatrix.sync.aligned.m8n8.x4.shared.b16 {%0,%1,%2,%3}, [%4];" \
    : "=r"((R)[0]), "=r"((R)[1]), "=r"((R)[2]), "=r"((R)[3]) : "r"(addr))

#define LDSM4T(R, addr) asm volatile( \
    "ldmatrix.sync.aligned.m8n8.x4.trans.shared.b16 {%0,%1,%2,%3}, [%4];" \
    : "=r"((R)[0]), "=r"((R)[1]), "=r"((R)[2]), "=r"((R)[3]) : "r"(addr))

#define MMA16816(AC, A, B0, B1) asm volatile( \
    "mma.sync.aligned.m16n8k16.row.col.f32.f16.f16.f32 " \
    "{%0,%1,%2,%3},{%4,%5,%6,%7},{%8,%9},{%0,%1,%2,%3};" \
    : "+f"((AC)[0]), "+f"((AC)[1]), "+f"((AC)[2]), "+f"((AC)[3]) \
    : "r"((A)[0]), "r"((A)[1]), "r"((A)[2]), "r"((A)[3]), "r"(B0), "r"(B1))

#define CPA16(dst, src) asm volatile( \
    "cp.async.cg.shared.global [%0], [%1], 16;" :: "r"(dst), "l"(src))

// ---------------- single-term fp16 tensor-core GEMM (templated tile) -------
// C = op(alpha * A@B + bias). A: [M,K] row-major. B: [K,N] row-major.
// M%128==0, N%BNT==0, K%32==0. Warp tile 64 x (BNT/4).
template <int BNT, int MINB>
__global__ __launch_bounds__(256, MINB)
void gemm_f16_t(const __half* __restrict__ Ah, const __half* __restrict__ Bh,
                const float* __restrict__ bias,
                float* __restrict__ Cf, __half* __restrict__ Ch,
                int K, int lda, int ldb, int ldc,
                long long sA, long long sB, long long sC,
                float alpha, int doBias, int doRelu)
{
    constexpr int BPITCH = BNT + 8;              // halfs per B smem row
    constexpr int B_PL_B = BK * BPITCH * 2;      // B plane bytes
    constexpr int STAGE_B = A_PL_B + B_PL_B;
    constexpr int NI = BNT / 32;                 // n8 frags per warp
    constexpr int NP = BNT / 64;                 // B ldsm ops per kk
    constexpr int WC = BNT / 4;                  // warp col span
    constexpr int BCHK = BNT / 8;                // 16B chunks per B row

    extern __shared__ char smem[];
    const unsigned smemS = (unsigned)__cvta_generic_to_shared(smem);
    const int tid = threadIdx.x, lane = tid & 31, w = tid >> 5;

    const int bz = blockIdx.z;
    const int rowTile = blockIdx.y * BM, colTile = blockIdx.x * BNT;
    const __half* pA = Ah + (long long)bz * sA + (long long)rowTile * lda;
    const __half* pB = Bh + (long long)bz * sB + colTile;
    const long long cOff = (long long)bz * sC;

    const int wRow = (w >> 2) * 64, wCol = (w & 3) * WC;

    const int aR0 = tid >> 2,  aP0 = tid & 3;

    const int nT = K / BK;

    auto load_stage = [&](int slot, int k0) {
        const unsigned base = smemS + (unsigned)slot * STAGE_B;
#pragma unroll
        for (int i = 0; i < 2; i++) {
            const int ar = aR0 + i * 64;
            CPA16(base + (unsigned)(ar * (APITCH * 2) + aP0 * 16),
                  pA + (long long)ar * lda + k0 + aP0 * 8);
        }
#pragma unroll
        for (int i = 0; i < NP; i++) {
            const int u = tid + i * 256;
            const int br = u / BCHK, bp = u % BCHK;
            CPA16(base + A_PL_B + (unsigned)(br * (BPITCH * 2) + bp * 16),
                  pB + (long long)(k0 + br) * ldb + bp * 8);
        }
        asm volatile("cp.async.commit_group;");
    };

    const int aLR = lane & 15, aLC = (lane >> 4) * 8;
    const int bLR = ((lane >> 3) & 1) * 8 + (lane & 7);
    const int bLC = (lane >> 4) * 8;

    float acc[4][NI][4];
#pragma unroll
    for (int i = 0; i < 4; i++)
#pragma unroll
        for (int j = 0; j < NI; j++)
#pragma unroll
            for (int e = 0; e < 4; e++) acc[i][j][e] = 0.f;

    load_stage(0, 0);
    load_stage(1, (1 < nT ? 1 : nT - 1) * BK);
    load_stage(2, (2 < nT ? 2 : nT - 1) * BK);

    for (int t = 0; t < nT; ++t) {
        asm volatile("cp.async.wait_group 2;" ::: "memory");
        __syncthreads();
        {
            const int s = t + 3;
            load_stage((t + 3) & (STAGES - 1), (s < nT ? s : nT - 1) * BK);
        }
        const unsigned sb = smemS + (unsigned)(t & (STAGES - 1)) * STAGE_B;
#pragma unroll
        for (int kk = 0; kk < 2; kk++) {
            unsigned ah[4][4], bh[NP][4];
#pragma unroll
            for (int mi = 0; mi < 4; mi++) {
                unsigned adr = sb +
                    (unsigned)(((wRow + mi * 16 + aLR) * APITCH + kk * 16 + aLC) << 1);
                LDSM4(ah[mi], adr);
            }
#pragma unroll
            for (int np = 0; np < NP; np++) {
                unsigned adr = sb + A_PL_B +
                    (unsigned)(((kk * 16 + bLR) * BPITCH + wCol + np * 16 + bLC) << 1);
                LDSM4T(bh[np], adr);
            }
#pragma unroll
            for (int mi = 0; mi < 4; mi++)
#pragma unroll
                for (int ni = 0; ni < NI; ni++)
                    MMA16816(acc[mi][ni], ah[mi], bh[ni >> 1][(ni & 1) * 2], bh[ni >> 1][(ni & 1) * 2 + 1]);
        }
    }

    // epilogue
#pragma unroll
    for (int mi = 0; mi < 4; mi++)
#pragma unroll
        for (int ni = 0; ni < NI; ni++) {
            const int r0 = rowTile + wRow + mi * 16 + (lane >> 2);
            const int c  = colTile + wCol + ni * 8 + (lane & 3) * 2;
            float* a = acc[mi][ni];
#pragma unroll
            for (int hrow = 0; hrow < 2; hrow++) {
                const int r = r0 + hrow * 8;
                float o0 = alpha * a[hrow * 2 + 0];
                float o1 = alpha * a[hrow * 2 + 1];
                if (doBias) { o0 += bias[c]; o1 += bias[c + 1]; }
                if (doRelu) { o0 = fmaxf(o0, 0.f); o1 = fmaxf(o1, 0.f); }
                const long long idx = cOff + (long long)r * ldc + c;
                if (Cf) {
                    *(float2*)&Cf[idx] = make_float2(o0, o1);
                } else {
                    __half2 p; p.x = __float2half_rn(o0); p.y = __float2half_rn(o1);
                    *(__half2*)&Ch[idx] = p;
                }
            }
        }
}

// ---------------- batched fp32 -> fp16 convert (up to 4 tensors) -----------
__global__ __launch_bounds__(256)
void conv4_kernel(const float* __restrict__ s0, const float* __restrict__ s1,
                  const float* __restrict__ s2, const float* __restrict__ s3,
                  __half* __restrict__ o0, __half* __restrict__ o1,
                  __half* __restrict__ o2, __half* __restrict__ o3,
                  long long n0, long long n1, long long n2, long long n3)
{
    long long i = ((long long)blockIdx.x * 256 + threadIdx.x) * 8;
    const float* s; __half* o;
    if (i < n0)                     { s = s0; o = o0; }
    else if ((i -= n0) < n1)        { s = s1; o = o1; }
    else if ((i -= n1) < n2)        { s = s2; o = o2; }
    else if ((i -= n2) < n3)        { s = s3; o = o3; }
    else return;
    float4 v0 = *(const float4*)(s + i);
    float4 v1 = *(const float4*)(s + i + 4);
    __half2 r[4];
    r[0].x = __float2half_rn(v0.x); r[0].y = __float2half_rn(v0.y);
    r[1].x = __float2half_rn(v0.z); r[1].y = __float2half_rn(v0.w);
    r[2].x = __float2half_rn(v1.x); r[2].y = __float2half_rn(v1.y);
    r[3].x = __float2half_rn(v1.z); r[3].y = __float2half_rn(v1.w);
    *(uint4*)&o[i] = *(uint4*)r;
}

// ---------------- rank-4 relative projections ----------------
__global__ void rproj_kernel(const float* __restrict__ rh,
                             const float* __restrict__ Wrq,
                             const float* __restrict__ Wrk,
                             float* __restrict__ rq, float* __restrict__ rk)
{
    const int i = blockIdx.x * blockDim.x + threadIdx.x;
    if (i >= BL_) return;
    const float h0 = rh[i * 4 + 0], h1v = rh[i * 4 + 1];
    const float h2 = rh[i * 4 + 2], h3 = rh[i * 4 + 3];
#pragma unroll
    for (int r = 0; r < 4; r++) {
        rq[i * 4 + r] = h0 * Wrq[r] + h1v * Wrq[4 + r] + h2 * Wrq[8 + r] + h3 * Wrq[12 + r];
        rk[i * 4 + r] = h0 * Wrk[r] + h1v * Wrk[4 + r] + h2 * Wrk[8 + r] + h3 * Wrk[12 + r];
    }
}

// ---------------- block reduction ----------------
__device__ __forceinline__ float blockReduce(float v, float* red, bool isMax)
{
    __syncthreads();
#pragma unroll
    for (int o = 16; o > 0; o >>= 1) {
        float t = __shfl_xor_sync(0xffffffffu, v, o);
        v = isMax ? fmaxf(v, t) : (v + t);
    }
    const int warp = threadIdx.x >> 5, lane = threadIdx.x & 31;
    if (lane == 0) red[warp] = v;
    __syncthreads();
    if (warp == 0) {
        v = (lane < 8) ? red[lane] : (isMax ? -INFINITY : 0.f);
#pragma unroll
        for (int o = 4; o > 0; o >>= 1) {
            float t = __shfl_xor_sync(0xffffffffu, v, o);
            v = isMax ? fmaxf(v, t) : (v + t);
        }
        if (lane == 0) red[0] = v;
    }
    __syncthreads();
    return red[0];
}

// ---------------- fused rel-bias + softmax -> fp16 ----------------
__global__ __launch_bounds__(256)
void softmax_bias_kernel(const float* __restrict__ S,
                         const float* __restrict__ rq,
                         const float* __restrict__ rk,
                         __half* __restrict__ Ph)
{
    __shared__ float red[32];
    const int l = blockIdx.x, n = blockIdx.y, b = blockIdx.z;
    const long long rowOff = ((((long long)b * NH_ + n) * L_) + l) * L_;
    const float* row = S + rowOff;
    const float* rqp = rq + ((long long)b * L_ + l) * 4;
    const float* rkp = rk + (long long)b * L_ * 4;
    const float q0 = rqp[0] * 0.5f, q1 = rqp[1] * 0.5f;
    const float q2 = rqp[2] * 0.5f, q3 = rqp[3] * 0.5f;
    const int tid = threadIdx.x;

    float vals[8];
    float vmax = -INFINITY;
#pragma unroll
    for (int j = 0; j < 8; j++) {
        const int m = j * 256 + tid;
        const float bias = q0 * rkp[m] + q1 * rkp[L_ + m]
                         + q2 * rkp[2 * L_ + m] + q3 * rkp[3 * L_ + m];
        const float v = row[m] + bias;
        vals[j] = v;
        vmax = fmaxf(vmax, v);
    }
    vmax = blockReduce(vmax, red, true);

    float sum = 0.f;
#pragma unroll
    for (int j = 0; j < 8; j++) {
        vals[j] = __expf(vals[j] - vmax);
        sum += vals[j];
    }
    sum = blockReduce(sum, red, false);
    const float inv = 1.f / sum;
#pragma unroll
    for (int j = 0; j < 8; j++)
        Ph[rowOff + j * 256 + tid] = __float2half_rn(vals[j] * inv);
}

// ---------------- fused residual-add + LayerNorm (+ optional fp16 out) -----
__global__ __launch_bounds__(256)
void add_ln_kernel(const float* __restrict__ x, const float* __restrict__ y,
                   const float* __restrict__ g, const float* __restrict__ be,
                   float* __restrict__ outF, __half* __restrict__ outH)
{
    __shared__ float red[32];
    const long long row = blockIdx.x;
    const float* xp = x + row * D_;
    const float* yp = y + row * D_;
    const int tid = threadIdx.x;

    float v[4];
    float s = 0.f;
#pragma unroll
    for (int j = 0; j < 4; j++) {
        const int i = j * 256 + tid;
        v[j] = xp[i] + yp[i];
        s += v[j];
    }
    const float mean = blockReduce(s, red, false) * (1.f / D_);

    float sq = 0.f;
#pragma unroll
    for (int j = 0; j < 4; j++) {
        const float d = v[j] - mean;
        sq += d * d;
    }
    const float var = blockReduce(sq, red, false) * (1.f / D_);
    const float rstd = rsqrtf(var + LN_EPS);
#pragma unroll
    for (int j = 0; j < 4; j++) {
        const int i = j * 256 + tid;
        const float o = (v[j] - mean) * rstd * g[i] + be[i];
        outF[row * D_ + i] = o;
        if (outH) outH[row * D_ + i] = __float2half_rn(o);
    }
}

// ---------------- host helpers ----------------
#define SMEM_256 (STAGES * (A_PL_B + BK * (256 + 8) * 2))   // 108544
#define SMEM_128 (STAGES * (A_PL_B + BK * (128 + 8) * 2))   // 75776

static void gemm256(const __half* Ah, const __half* Bh,
                    const float* bias, float* Cf, __half* Ch,
                    int M, int N, int K, int lda, int ldb, int ldc,
                    long long sA, long long sB, long long sC, int batch,
                    float alpha, int doBias, int doRelu)
{
    dim3 grid(N / 256, M / BM, batch), block(256);
    gemm_f16_t<256, 1><<<grid, block, SMEM_256>>>(Ah, Bh, bias, Cf, Ch,
                                                  K, lda, ldb, ldc, sA, sB, sC,
                                                  alpha, doBias, doRelu);
}

static void gemm128(const __half* Ah, const __half* Bh,
                    const float* bias, float* Cf, __half* Ch,
                    int M, int N, int K, int lda, int ldb, int ldc,
                    long long sA, long long sB, long long sC, int batch,
                    float alpha, int doBias, int doRelu)
{
    dim3 grid(N / 128, M / BM, batch), block(256);
    gemm_f16_t<128, 2><<<grid, block, SMEM_128>>>(Ah, Bh, bias, Cf, Ch,
                                                  K, lda, ldb, ldc, sA, sB, sC,
                                                  alpha, doBias, doRelu);
}

template <typename T>
static T* sym(T* symbol) { void* p; cudaGetSymbolAddress(&p, (const void*)symbol); return (T*)p; }

extern "C" void kernel_launch(void* const* d_in, const int* in_sizes, int n_in,
                              void* d_out, int out_size)
{
    const float* h   = (const float*)d_in[0];
    const float* rh  = (const float*)d_in[1];
    const float* Wq  = (const float*)d_in[2];
    const float* Wk  = (const float*)d_in[3];
    const float* Wv  = (const float*)d_in[4];
    const float* Wo  = (const float*)d_in[5];
    const float* Wrk = (const float*)d_in[6];
    const float* Wrq = (const float*)d_in[7];
    const float* W1  = (const float*)d_in[8];
    const float* b1  = (const float*)d_in[9];
    const float* W2  = (const float*)d_in[10];
    const float* b2  = (const float*)d_in[11];
    const float* g1  = (const float*)d_in[12];
    const float* be1 = (const float*)d_in[13];
    const float* g2  = (const float*)d_in[14];
    const float* be2 = (const float*)d_in[15];
    float* out = (float*)d_out;

    cudaFuncSetAttribute(gemm_f16_t<256, 1>,
                         cudaFuncAttributeMaxDynamicSharedMemorySize, SMEM_256);
    cudaFuncSetAttribute(gemm_f16_t<128, 2>,
                         cudaFuncAttributeMaxDynamicSharedMemorySize, SMEM_128);

    __half *hh = sym(g_hh);
    __half *Wqh = sym(g_Wqh), *Wkh = sym(g_Wkh), *Wvh = sym(g_Wvh), *Woh = sym(g_Woh);
    __half *W1h = sym(g_W1h), *W2h = sym(g_W2h);
    __half *qh = sym(g_qh), *kh = sym(g_kh), *vh = sym(g_vh);
    __half *ch = sym(g_ch), *h1h = sym(g_h1h), *fh = sym(g_fh);
    __half *Ph = sym(g_Ph);
    float *S = sym(g_S), *hsa = sym(g_hsa), *h1 = sym(g_h1), *hf = sym(g_hf);
    float *rq = sym(g_rq), *rk = sym(g_rk);

    const long long nH = (long long)BL_ * D_;      // 4M
    const long long nW = (long long)D_ * D_;       // 1M
    const long long nF = (long long)D_ * FFN_;     // 4M

    // 0) convert h, Wq, Wk, Wv
    conv4_kernel<<<(int)((nH + 3 * nW) / 2048), 256>>>(
        h, Wq, Wk, Wv, hh, Wqh, Wkh, Wvh, nH, nW, nW, nW);
    // 1-3) QKV projections (BN=256: grid 4x32 = 128 CTAs, one wave)
    gemm256(hh, Wqh, nullptr, nullptr, qh, BL_, D_, D_, D_, D_, D_, 0, 0, 0, 1, 1.f, 0, 0);
    gemm256(hh, Wkh, nullptr, nullptr, kh, BL_, D_, D_, D_, D_, D_, 0, 0, 0, 1, 1.f, 0, 0);
    gemm256(hh, Wvh, nullptr, nullptr, vh, BL_, D_, D_, D_, D_, D_, 0, 0, 0, 1, 1.f, 0, 0);
    // 4) scores: per (b,head), S = Q[2048x128] @ Kt[128x2048] / sqrt(HD)
    gemm256(qh, kh, nullptr, S, nullptr, L_, L_, HD_, HD_, L_, L_,
            CHUNK_, CHUNK_, (long long)L_ * L_, B_ * NH_, RSQRT_HD, 0, 0);
    // 5) rank-4 projections
    rproj_kernel<<<BL_ / 256, 256>>>(rh, Wrq, Wrk, rq, rk);
    // 6) convert Wo, W1, W2
    conv4_kernel<<<(int)((nW + 2 * nF) / 2048), 256>>>(
        Wo, W1, W2, nullptr, Woh, W1h, W2h, nullptr, nW, nF, nF, 0);
    // 7) fused rel-bias + softmax -> P fp16
    {
        dim3 grid(L_, NH_, B_);
        softmax_bias_kernel<<<grid, 256>>>(S, rq, rk, Ph);
    }
    // 8) context: P[2048x2048] @ V[2048x128]  (N=128 -> narrow kernel)
    gemm128(Ph, vh, nullptr, nullptr, ch, L_, HD_, L_, L_, HD_, HD_,
            (long long)L_ * L_, CHUNK_, CHUNK_, B_ * NH_, 1.f, 0, 0);
    // 9) output projection
    gemm256(ch, Woh, nullptr, hsa, nullptr, BL_, D_, D_, D_, D_, D_, 0, 0, 0, 1, 1.f, 0, 0);
    // 10) h1 = LN(hsa + h)
    add_ln_kernel<<<BL_, 256>>>(hsa, h, g1, be1, h1, h1h);
    // 11) FFN up: relu(h1 @ W1 + b1)
    gemm256(h1h, W1h, b1, nullptr, fh, BL_, FFN_, D_, D_, FFN_, FFN_, 0, 0, 0, 1, 1.f, 1, 1);
    // 12) FFN down: ffn @ W2 + b2
    gemm256(fh, W2h, b2, hf, nullptr, BL_, D_, FFN_, FFN_, D_, D_, 0, 0, 0, 1, 1.f, 1, 0);
    // 13) h2 = LN(h1 + hf) -> out
    add_ln_kernel<<<BL_, 256>>>(h1, hf, g2, be2, out, nullptr);
}